// round 4
// baseline (speedup 1.0000x reference)
#include <cuda_runtime.h>
#include <cuda_bf16.h>
#include <cstdint>

#define NB 8
#define TDIM 4096
#define SDIM 512
#define CDIM 1024
#define NCHUNK 16
#define CHROWS (TDIM / NCHUNK)
#define NEG_INF (-3.0e38f)

typedef __nv_bfloat16 bf16;

// ---------------- scratch (static device globals; no allocation) ----------------
__device__ float g_sc [(size_t)NB * TDIM * SDIM];
__device__ float g_vsc[(size_t)NB * SDIM * TDIM];
__device__ __align__(16) bf16 g_Xh [(size_t)NB * TDIM * CDIM], g_Xl [(size_t)NB * TDIM * CDIM];
__device__ __align__(16) bf16 g_XTh[(size_t)NB * CDIM * TDIM], g_XTl[(size_t)NB * CDIM * TDIM];
__device__ __align__(16) bf16 g_Kh [(size_t)NB * SDIM * CDIM], g_Kl [(size_t)NB * SDIM * CDIM];
__device__ __align__(16) bf16 g_Vh [(size_t)NB * SDIM * CDIM], g_Vl [(size_t)NB * SDIM * CDIM];
__device__ __align__(16) bf16 g_VTh[(size_t)NB * CDIM * SDIM], g_VTl[(size_t)NB * CDIM * SDIM];
__device__ __align__(16) bf16 g_Ph [(size_t)NB * TDIM * SDIM], g_Pl [(size_t)NB * TDIM * SDIM];
__device__ __align__(16) bf16 g_P2h[(size_t)NB * SDIM * TDIM], g_P2l[(size_t)NB * SDIM * TDIM];
__device__ __align__(16) bf16 g_P3h[(size_t)NB * SDIM * TDIM], g_P3l[(size_t)NB * SDIM * TDIM];
__device__ float g_pcm[NB * NCHUNK * SDIM], g_pcs[NB * NCHUNK * SDIM];
__device__ float g_cm [NB * SDIM], g_cs [NB * SDIM];

// ---------------- PTX helpers (sm_80-class; no tcgen05 in compute_103 PTX) ----------------
__device__ __forceinline__ void cp16(uint32_t dst, const void* src) {
    asm volatile("cp.async.cg.shared.global [%0], [%1], 16;" :: "r"(dst), "l"(src));
}
__device__ __forceinline__ void cp_commit() {
    asm volatile("cp.async.commit_group;" ::: "memory");
}
template <int N>
__device__ __forceinline__ void cp_wait() {
    asm volatile("cp.async.wait_group %0;" :: "n"(N) : "memory");
}
__device__ __forceinline__ void ldsm4(uint32_t* r, uint32_t addr) {
    asm volatile("ldmatrix.sync.aligned.m8n8.x4.shared.b16 {%0,%1,%2,%3}, [%4];"
                 : "=r"(r[0]), "=r"(r[1]), "=r"(r[2]), "=r"(r[3]) : "r"(addr));
}
__device__ __forceinline__ void mma16816(float* d, const uint32_t* a, const uint32_t* b) {
    asm volatile(
        "mma.sync.aligned.m16n8k16.row.col.f32.bf16.bf16.f32 "
        "{%0,%1,%2,%3}, {%4,%5,%6,%7}, {%8,%9}, {%0,%1,%2,%3};"
        : "+f"(d[0]), "+f"(d[1]), "+f"(d[2]), "+f"(d[3])
        : "r"(a[0]), "r"(a[1]), "r"(a[2]), "r"(a[3]), "r"(b[0]), "r"(b[1]));
}
__device__ __forceinline__ void split1(float f, bf16& h, bf16& l) {
    h = __float2bfloat16_rn(f);
    l = __float2bfloat16_rn(f - __bfloat162float(h));
}

// ---------------------------------------------------------------------------
// bf16x3 emulated-fp32 GEMM on HMMA. Tile 256(M) x 128(N), BK=32, 512 thr,
// 16 warps (warp tile 64x32), 3-stage cp.async pipeline, 1 sync per chunk.
// ---------------------------------------------------------------------------
#define ROWB 80
#define AROWS 256
#define BROWS 128
#define ATILE (AROWS * ROWB)              // 20480
#define BTILE (BROWS * ROWB)              // 10240
#define STAGE (2 * ATILE + 2 * BTILE)     // 61440

template <bool ADD>
__global__ void __launch_bounds__(512, 1)
mma_gemm(const bf16* __restrict__ Ah, const bf16* __restrict__ Al,
         const bf16* __restrict__ Bh, const bf16* __restrict__ Bl,
         const float* __restrict__ Res, float* __restrict__ C,
         float scale, int K, int Nglob, size_t sA, size_t sB, size_t sC)
{
    extern __shared__ char dsm[];
    const uint32_t sbase = (uint32_t)__cvta_generic_to_shared(dsm);
    const int tid = threadIdx.x, wid = tid >> 5, lane = tid & 31;
    const int b = blockIdx.z, m0 = blockIdx.y * 256, n0 = blockIdx.x * 128;
    const int wm = wid & 3, wn = wid >> 2;          // 4x4 warps, warp tile 64x32

    const bf16* pA[2] = {Ah + (size_t)b * sA, Al + (size_t)b * sA};
    const bf16* pB[2] = {Bh + (size_t)b * sB, Bl + (size_t)b * sB};

    const int KT = K >> 5;

    auto load = [&](int kc, int s) {
        uint32_t st = sbase + s * STAGE;
#pragma unroll
        for (int t = 0; t < 2; t++) {                 // Ah, Al
#pragma unroll
            for (int i = 0; i < 2; i++) {
                int idx = tid + i * 512;
                int r = idx >> 2, c = idx & 3;
                cp16(st + t * ATILE + r * ROWB + c * 16,
                     (const char*)pA[t] + ((size_t)(m0 + r) * K + kc * 32 + c * 8) * 2);
            }
        }
#pragma unroll
        for (int t = 0; t < 2; t++) {                 // Bh, Bl
            int r = tid >> 2, c = tid & 3;
            cp16(st + 2 * ATILE + t * BTILE + r * ROWB + c * 16,
                 (const char*)pB[t] + ((size_t)(n0 + r) * K + kc * 32 + c * 8) * 2);
        }
        cp_commit();
    };

    float acc[4][4][4];
#pragma unroll
    for (int mi = 0; mi < 4; mi++)
#pragma unroll
        for (int ni = 0; ni < 4; ni++)
#pragma unroll
            for (int j = 0; j < 4; j++) acc[mi][ni][j] = 0.f;

    const uint32_t a_off = (uint32_t)((wm * 64 + (lane & 15)) * ROWB + (lane >> 4) * 16);
    const uint32_t b_row = (uint32_t)(wn * 32 + (lane & 7) + ((lane >> 4) << 3));
    const uint32_t b_off = b_row * ROWB + ((lane >> 3) & 1) * 16;

    auto compute = [&](int s) {
        uint32_t st = sbase + s * STAGE;
        uint32_t ahb = st + a_off;
        uint32_t alb = st + ATILE + a_off;
        uint32_t bhb = st + 2 * ATILE + b_off;
        uint32_t blb = st + 2 * ATILE + BTILE + b_off;
#pragma unroll
        for (int ks = 0; ks < 2; ks++) {
            uint32_t ah[4][4], al[4][4];
#pragma unroll
            for (int mi = 0; mi < 4; mi++) {
                ldsm4(ah[mi], ahb + mi * (16 * ROWB) + ks * 32);
                ldsm4(al[mi], alb + mi * (16 * ROWB) + ks * 32);
            }
#pragma unroll
            for (int j = 0; j < 2; j++) {
                uint32_t bh[4], bl[4];
                ldsm4(bh, bhb + j * (16 * ROWB) + ks * 32);
                ldsm4(bl, blb + j * (16 * ROWB) + ks * 32);
#pragma unroll
                for (int mi = 0; mi < 4; mi++) {
                    mma16816(acc[mi][2 * j],     ah[mi], bh);
                    mma16816(acc[mi][2 * j],     al[mi], bh);
                    mma16816(acc[mi][2 * j],     ah[mi], bl);
                    mma16816(acc[mi][2 * j + 1], ah[mi], bh + 2);
                    mma16816(acc[mi][2 * j + 1], al[mi], bh + 2);
                    mma16816(acc[mi][2 * j + 1], ah[mi], bl + 2);
                }
            }
        }
    };

    load(0, 0);
    if (KT > 1) load(1, 1);

    for (int ci = 0; ci < KT; ci++) {
        if (ci < KT - 1) cp_wait<1>(); else cp_wait<0>();
        __syncthreads();
        if (ci + 2 < KT) load(ci + 2, (ci + 2) % 3);
        compute(ci % 3);
    }

    // epilogue
    float* Co = C + (size_t)b * sC;
    const float* Rp = ADD ? (Res + (size_t)b * sC) : nullptr;
    const int rbase = m0 + wm * 64 + (lane >> 2);
    const int cbase = n0 + wn * 32 + (lane & 3) * 2;
#pragma unroll
    for (int mi = 0; mi < 4; mi++) {
#pragma unroll
        for (int ni = 0; ni < 4; ni++) {
#pragma unroll
            for (int h = 0; h < 2; h++) {
                int r = rbase + mi * 16 + h * 8;
                int c = cbase + ni * 8;
                float2 v;
                v.x = acc[mi][ni][2 * h]     * scale;
                v.y = acc[mi][ni][2 * h + 1] * scale;
                size_t go = (size_t)r * Nglob + c;
                if (ADD) {
                    float2 d = *(const float2*)(Rp + go);
                    v.x += d.x; v.y += d.y;
                }
                *(float2*)(Co + go) = v;
            }
        }
    }
}

// ---------------- fused conversion kernels ----------------
// split + transposed split in one pass (reads source once)
__global__ void stx_k(const float* __restrict__ in, bf16* __restrict__ oh,
                      bf16* __restrict__ ol, bf16* __restrict__ ohT,
                      bf16* __restrict__ olT, int R, int Cc)
{
    __shared__ float t[32][33];
    int b = blockIdx.z;
    int c0 = blockIdx.x * 32, r0 = blockIdx.y * 32;
    const float* ip = in + (size_t)b * R * Cc;
    size_t nb = (size_t)b * R * Cc;       // same element count both layouts
    int tx = threadIdx.x, ty = threadIdx.y;
#pragma unroll
    for (int i = 0; i < 4; i++) {
        int r = r0 + ty + i * 8;
        float v = ip[(size_t)r * Cc + c0 + tx];
        t[ty + i * 8][tx] = v;
        bf16 h, l;
        split1(v, h, l);
        oh[nb + (size_t)r * Cc + c0 + tx] = h;
        ol[nb + (size_t)r * Cc + c0 + tx] = l;
    }
    __syncthreads();
#pragma unroll
    for (int i = 0; i < 4; i++) {
        int c = c0 + ty + i * 8;
        bf16 h, l;
        split1(t[tx][ty + i * 8], h, l);
        ohT[nb + (size_t)c * R + r0 + tx] = h;
        olT[nb + (size_t)c * R + r0 + tx] = l;
    }
}

__global__ void split_k(const float* __restrict__ in, bf16* __restrict__ h,
                        bf16* __restrict__ l, size_t n4)
{
    size_t i = (size_t)blockIdx.x * blockDim.x + threadIdx.x;
    if (i >= n4) return;
    float4 v = ((const float4*)in)[i];
    bf16 h0, l0, h1, l1, h2, l2, h3, l3;
    split1(v.x, h0, l0); split1(v.y, h1, l1); split1(v.z, h2, l2); split1(v.w, h3, l3);
    __nv_bfloat162* hp = (__nv_bfloat162*)h;
    __nv_bfloat162* lp = (__nv_bfloat162*)l;
    hp[i * 2]     = __nv_bfloat162(h0, h1);
    hp[i * 2 + 1] = __nv_bfloat162(h2, h3);
    lp[i * 2]     = __nv_bfloat162(l0, l1);
    lp[i * 2 + 1] = __nv_bfloat162(l2, l3);
}

// fused row softmax (len 512) + bf16 split; warp per row, single pass
__global__ void softrow512_k(const float* __restrict__ S, bf16* __restrict__ oh,
                             bf16* __restrict__ ol)
{
    int warp = threadIdx.x >> 5, lane = threadIdx.x & 31;
    size_t row = (size_t)blockIdx.x * 8 + warp;
    const float4* p4 = (const float4*)(S + row * SDIM);
    float4 v[4];
    float m = NEG_INF;
#pragma unroll
    for (int i = 0; i < 4; i++) {
        v[i] = p4[lane + i * 32];
        m = fmaxf(m, fmaxf(fmaxf(v[i].x, v[i].y), fmaxf(v[i].z, v[i].w)));
    }
#pragma unroll
    for (int o = 16; o > 0; o >>= 1) m = fmaxf(m, __shfl_xor_sync(0xffffffffu, m, o));
    float s = 0.f;
#pragma unroll
    for (int i = 0; i < 4; i++)
        s += __expf(v[i].x - m) + __expf(v[i].y - m) + __expf(v[i].z - m) + __expf(v[i].w - m);
#pragma unroll
    for (int o = 16; o > 0; o >>= 1) s += __shfl_xor_sync(0xffffffffu, s, o);
    float inv = __fdividef(1.0f, s);
    __nv_bfloat162* hp = (__nv_bfloat162*)(oh + row * SDIM);
    __nv_bfloat162* lp = (__nv_bfloat162*)(ol + row * SDIM);
#pragma unroll
    for (int i = 0; i < 4; i++) {
        bf16 h0, l0, h1, l1, h2, l2, h3, l3;
        split1(__expf(v[i].x - m) * inv, h0, l0);
        split1(__expf(v[i].y - m) * inv, h1, l1);
        split1(__expf(v[i].z - m) * inv, h2, l2);
        split1(__expf(v[i].w - m) * inv, h3, l3);
        int p = (lane + i * 32) * 2;
        hp[p]     = __nv_bfloat162(h0, h1);
        hp[p + 1] = __nv_bfloat162(h2, h3);
        lp[p]     = __nv_bfloat162(l0, l1);
        lp[p + 1] = __nv_bfloat162(l2, l3);
    }
}

// fused row softmax (len 4096) + bf16 split; block (512 thr) per row
__global__ void softrow4096_k(const float* __restrict__ S, bf16* __restrict__ oh,
                              bf16* __restrict__ ol)
{
    __shared__ float sh[16];
    int tid = threadIdx.x, lane = tid & 31, warp = tid >> 5;
    size_t row = blockIdx.x;
    const float4* p4 = (const float4*)(S + row * TDIM);
    float4 v[2];
    float m = NEG_INF;
#pragma unroll
    for (int i = 0; i < 2; i++) {
        v[i] = p4[tid + i * 512];
        m = fmaxf(m, fmaxf(fmaxf(v[i].x, v[i].y), fmaxf(v[i].z, v[i].w)));
    }
#pragma unroll
    for (int o = 16; o > 0; o >>= 1) m = fmaxf(m, __shfl_xor_sync(0xffffffffu, m, o));
    if (!lane) sh[warp] = m;
    __syncthreads();
    if (tid < 16) {
        float t = sh[tid];
#pragma unroll
        for (int o = 8; o > 0; o >>= 1) t = fmaxf(t, __shfl_xor_sync(0xffffu, t, o));
        if (!tid) sh[0] = t;
    }
    __syncthreads();
    m = sh[0];
    __syncthreads();
    float s = 0.f;
#pragma unroll
    for (int i = 0; i < 2; i++)
        s += __expf(v[i].x - m) + __expf(v[i].y - m) + __expf(v[i].z - m) + __expf(v[i].w - m);
#pragma unroll
    for (int o = 16; o > 0; o >>= 1) s += __shfl_xor_sync(0xffffffffu, s, o);
    if (!lane) sh[warp] = s;
    __syncthreads();
    if (tid < 16) {
        float t = sh[tid];
#pragma unroll
        for (int o = 8; o > 0; o >>= 1) t += __shfl_xor_sync(0xffffu, t, o);
        if (!tid) sh[0] = t;
    }
    __syncthreads();
    float inv = __fdividef(1.0f, sh[0]);
    __nv_bfloat162* hp = (__nv_bfloat162*)(oh + row * TDIM);
    __nv_bfloat162* lp = (__nv_bfloat162*)(ol + row * TDIM);
#pragma unroll
    for (int i = 0; i < 2; i++) {
        bf16 h0, l0, h1, l1, h2, l2, h3, l3;
        split1(__expf(v[i].x - m) * inv, h0, l0);
        split1(__expf(v[i].y - m) * inv, h1, l1);
        split1(__expf(v[i].z - m) * inv, h2, l2);
        split1(__expf(v[i].w - m) * inv, h3, l3);
        int p = (tid + i * 512) * 2;
        hp[p]     = __nv_bfloat162(h0, h1);
        hp[p + 1] = __nv_bfloat162(h2, h3);
        lp[p]     = __nv_bfloat162(l0, l1);
        lp[p + 1] = __nv_bfloat162(l2, l3);
    }
}

// ---------------- column softmax (over T) pipeline ----------------
__global__ void colpart_k(const float* __restrict__ S, float* __restrict__ pm,
                          float* __restrict__ ps)
{
    int b = blockIdx.y, ch = blockIdx.x, s = threadIdx.x;
    const float* p = S + (size_t)b * TDIM * SDIM + (size_t)ch * CHROWS * SDIM + s;
    float m = NEG_INF, sum = 0.f;
    for (int t = 0; t < CHROWS; t++) {
        float v = p[(size_t)t * SDIM];
        float nm = fmaxf(m, v);
        sum = sum * __expf(m - nm) + __expf(v - nm);
        m = nm;
    }
    int o = (b * NCHUNK + ch) * SDIM + s;
    pm[o] = m; ps[o] = sum;
}

__global__ void colcomb_k(const float* __restrict__ pm, const float* __restrict__ ps,
                          float* __restrict__ cm, float* __restrict__ cs)
{
    int b = blockIdx.x, s = threadIdx.x;
    float m = NEG_INF;
#pragma unroll
    for (int c = 0; c < NCHUNK; c++) m = fmaxf(m, pm[(b * NCHUNK + c) * SDIM + s]);
    float sum = 0.f;
#pragma unroll
    for (int c = 0; c < NCHUNK; c++)
        sum += ps[(b * NCHUNK + c) * SDIM + s] * __expf(pm[(b * NCHUNK + c) * SDIM + s] - m);
    cm[b * SDIM + s] = m;
    cs[b * SDIM + s] = sum;
}

__global__ void pcolT_k(const float* __restrict__ sc, const float* __restrict__ cm,
                        const float* __restrict__ cs, bf16* __restrict__ oh,
                        bf16* __restrict__ ol)
{
    __shared__ float t[32][33];
    int b = blockIdx.z;
    int s0 = blockIdx.x * 32, t0 = blockIdx.y * 32;
    const float* ip = sc + (size_t)b * TDIM * SDIM;
    int tx = threadIdx.x, ty = threadIdx.y;
#pragma unroll
    for (int i = 0; i < 4; i++)
        t[ty + i * 8][tx] = ip[(size_t)(t0 + ty + i * 8) * SDIM + s0 + tx];
    __syncthreads();
    size_t ob = (size_t)b * SDIM * TDIM;
#pragma unroll
    for (int i = 0; i < 4; i++) {
        int s = s0 + ty + i * 8;
        float m = cm[b * SDIM + s], inv = __fdividef(1.0f, cs[b * SDIM + s]);
        bf16 h, l;
        split1(__expf(t[tx][ty + i * 8] - m) * inv, h, l);
        oh[ob + (size_t)s * TDIM + t0 + tx] = h;
        ol[ob + (size_t)s * TDIM + t0 + tx] = l;
    }
}

// ---------------- launch ----------------
extern "C" void kernel_launch(void* const* d_in, const int* in_sizes, int n_in,
                              void* d_out, int out_size)
{
    const float* x   = (const float*)d_in[0];
    const float* kin = (const float*)d_in[1];
    const float* vin = (const float*)d_in[2];

    float* att = (float*)d_out;
    float* ktv = att + (size_t)NB * TDIM * CDIM;
    float* vtv = ktv + (size_t)NB * SDIM * CDIM;

    float *sc, *vsc, *pcm, *pcs, *cm, *cs;
    bf16 *Xh, *Xl, *XTh, *XTl, *Kh, *Kl, *Vh, *Vl, *VTh, *VTl;
    bf16 *Ph, *Pl, *P2h, *P2l, *P3h, *P3l;
    cudaGetSymbolAddress((void**)&sc, g_sc);     cudaGetSymbolAddress((void**)&vsc, g_vsc);
    cudaGetSymbolAddress((void**)&pcm, g_pcm);   cudaGetSymbolAddress((void**)&pcs, g_pcs);
    cudaGetSymbolAddress((void**)&cm, g_cm);     cudaGetSymbolAddress((void**)&cs, g_cs);
    cudaGetSymbolAddress((void**)&Xh, g_Xh);     cudaGetSymbolAddress((void**)&Xl, g_Xl);
    cudaGetSymbolAddress((void**)&XTh, g_XTh);   cudaGetSymbolAddress((void**)&XTl, g_XTl);
    cudaGetSymbolAddress((void**)&Kh, g_Kh);     cudaGetSymbolAddress((void**)&Kl, g_Kl);
    cudaGetSymbolAddress((void**)&Vh, g_Vh);     cudaGetSymbolAddress((void**)&Vl, g_Vl);
    cudaGetSymbolAddress((void**)&VTh, g_VTh);   cudaGetSymbolAddress((void**)&VTl, g_VTl);
    cudaGetSymbolAddress((void**)&Ph, g_Ph);     cudaGetSymbolAddress((void**)&Pl, g_Pl);
    cudaGetSymbolAddress((void**)&P2h, g_P2h);   cudaGetSymbolAddress((void**)&P2l, g_P2l);
    cudaGetSymbolAddress((void**)&P3h, g_P3h);   cudaGetSymbolAddress((void**)&P3l, g_P3l);

    const int SMEM = 3 * STAGE;  // 184320
    cudaFuncSetAttribute(mma_gemm<false>, cudaFuncAttributeMaxDynamicSharedMemorySize, SMEM);
    cudaFuncSetAttribute(mma_gemm<true>,  cudaFuncAttributeMaxDynamicSharedMemorySize, SMEM);

    const float scale = 0.03125f;  // 1/sqrt(1024)

    // operand prep (single-pass fused split + transposed split)
    stx_k<<<dim3(CDIM / 32, TDIM / 32, NB), dim3(32, 8)>>>(x, Xh, Xl, XTh, XTl, TDIM, CDIM);
    {
        size_t n4 = (size_t)NB * SDIM * CDIM / 4;
        split_k<<<(unsigned)((n4 + 255) / 256), 256>>>(kin, Kh, Kl, n4);
    }
    stx_k<<<dim3(CDIM / 32, SDIM / 32, NB), dim3(32, 8)>>>(vin, Vh, Vl, VTh, VTl, SDIM, CDIM);

    // 1) scores = scale * X K^T  [T,S]
    mma_gemm<false><<<dim3(SDIM / 128, TDIM / 256, NB), 512, SMEM>>>(
        Xh, Xl, Kh, Kl, nullptr, sc, scale, CDIM, SDIM,
        (size_t)TDIM * CDIM, (size_t)SDIM * CDIM, (size_t)TDIM * SDIM);

    // P (row softmax, fused), column stats + P2^T
    softrow512_k<<<NB * TDIM / 8, 256>>>(sc, Ph, Pl);
    colpart_k<<<dim3(NCHUNK, NB), 512>>>(sc, pcm, pcs);
    colcomb_k<<<NB, 512>>>(pcm, pcs, cm, cs);
    pcolT_k<<<dim3(SDIM / 32, TDIM / 32, NB), dim3(32, 8)>>>(sc, cm, cs, P2h, P2l);

    // 2) att = P V   (B = V^T [C,S], K=512)
    mma_gemm<false><<<dim3(CDIM / 128, TDIM / 256, NB), 512, SMEM>>>(
        Ph, Pl, VTh, VTl, nullptr, att, 1.0f, SDIM, CDIM,
        (size_t)TDIM * SDIM, (size_t)CDIM * SDIM, (size_t)TDIM * CDIM);

    // 3) k_t = k + P2^T X   (B = X^T [C,T], K=4096)
    mma_gemm<true><<<dim3(CDIM / 128, SDIM / 256, NB), 512, SMEM>>>(
        P2h, P2l, XTh, XTl, kin, ktv, 1.0f, TDIM, CDIM,
        (size_t)SDIM * TDIM, (size_t)CDIM * TDIM, (size_t)SDIM * CDIM);

    // 4) v_scores = scale * V X^T  [S,T]
    mma_gemm<false><<<dim3(TDIM / 128, SDIM / 256, NB), 512, SMEM>>>(
        Vh, Vl, Xh, Xl, nullptr, vsc, scale, CDIM, TDIM,
        (size_t)SDIM * CDIM, (size_t)TDIM * CDIM, (size_t)SDIM * TDIM);

    // P3 (row softmax over 4096, fused)
    softrow4096_k<<<NB * SDIM, 512>>>(vsc, P3h, P3l);

    // 5) v_t = v + P3 X   (B = X^T [C,T], K=4096)
    mma_gemm<true><<<dim3(CDIM / 128, SDIM / 256, NB), 512, SMEM>>>(
        P3h, P3l, XTh, XTl, vin, vtv, 1.0f, TDIM, CDIM,
        (size_t)SDIM * TDIM, (size_t)CDIM * TDIM, (size_t)SDIM * CDIM);
}

// round 5
// speedup vs baseline: 1.1094x; 1.1094x over previous
#include <cuda_runtime.h>
#include <cuda_bf16.h>
#include <cstdint>

#define NB 8
#define TDIM 4096
#define SDIM 512
#define CDIM 1024
#define NCHUNK 16
#define CHROWS (TDIM / NCHUNK)
#define NEG_INF (-3.0e38f)

typedef __nv_bfloat16 bf16;

// ---------------- scratch (static device globals; no allocation) ----------------
__device__ float g_sc [(size_t)NB * TDIM * SDIM];
__device__ float g_vsc[(size_t)NB * SDIM * TDIM];
__device__ __align__(16) bf16 g_Xh [(size_t)NB * TDIM * CDIM], g_Xl [(size_t)NB * TDIM * CDIM];
__device__ __align__(16) bf16 g_XTh[(size_t)NB * CDIM * TDIM], g_XTl[(size_t)NB * CDIM * TDIM];
__device__ __align__(16) bf16 g_Kh [(size_t)NB * SDIM * CDIM], g_Kl [(size_t)NB * SDIM * CDIM];
__device__ __align__(16) bf16 g_Vh [(size_t)NB * SDIM * CDIM], g_Vl [(size_t)NB * SDIM * CDIM];
__device__ __align__(16) bf16 g_VTh[(size_t)NB * CDIM * SDIM], g_VTl[(size_t)NB * CDIM * SDIM];
__device__ __align__(16) bf16 g_Ph [(size_t)NB * TDIM * SDIM], g_Pl [(size_t)NB * TDIM * SDIM];
__device__ __align__(16) bf16 g_P2h[(size_t)NB * SDIM * TDIM], g_P2l[(size_t)NB * SDIM * TDIM];
__device__ __align__(16) bf16 g_P3h[(size_t)NB * SDIM * TDIM], g_P3l[(size_t)NB * SDIM * TDIM];
__device__ float g_pcm[NB * NCHUNK * SDIM], g_pcs[NB * NCHUNK * SDIM];
__device__ float g_cm [NB * SDIM], g_cs [NB * SDIM];

// ---------------- PTX helpers ----------------
__device__ __forceinline__ void cp16(uint32_t dst, const void* src) {
    asm volatile("cp.async.cg.shared.global [%0], [%1], 16;" :: "r"(dst), "l"(src));
}
__device__ __forceinline__ void cp_commit() {
    asm volatile("cp.async.commit_group;" ::: "memory");
}
template <int N>
__device__ __forceinline__ void cp_wait() {
    asm volatile("cp.async.wait_group %0;" :: "n"(N) : "memory");
}
__device__ __forceinline__ void ldsm4(uint32_t* r, uint32_t addr) {
    asm volatile("ldmatrix.sync.aligned.m8n8.x4.shared.b16 {%0,%1,%2,%3}, [%4];"
                 : "=r"(r[0]), "=r"(r[1]), "=r"(r[2]), "=r"(r[3]) : "r"(addr));
}
__device__ __forceinline__ void mma16816(float* d, const uint32_t* a, const uint32_t* b) {
    asm volatile(
        "mma.sync.aligned.m16n8k16.row.col.f32.bf16.bf16.f32 "
        "{%0,%1,%2,%3}, {%4,%5,%6,%7}, {%8,%9}, {%0,%1,%2,%3};"
        : "+f"(d[0]), "+f"(d[1]), "+f"(d[2]), "+f"(d[3])
        : "r"(a[0]), "r"(a[1]), "r"(a[2]), "r"(a[3]), "r"(b[0]), "r"(b[1]));
}
__device__ __forceinline__ void split1(float f, bf16& h, bf16& l) {
    h = __float2bfloat16_rn(f);
    l = __float2bfloat16_rn(f - __bfloat162float(h));
}

// ---------------------------------------------------------------------------
// bf16x3 emulated-fp32 GEMM on HMMA. Tile 128x128, BK=32, 256 thr, 8 warps
// (warp tile 64x32). SMEM: hi|lo planes packed in one 128B SW128 row ->
// stage 32KB, 3 stages = 96KB, 2 CTAs/SM. One sync per chunk, pass-major MMA.
// ---------------------------------------------------------------------------
#define STAGE 32768
#define BOFF  16384

template <bool ADD>
__global__ void __launch_bounds__(256, 2)
mma_gemm(const bf16* __restrict__ Ah, const bf16* __restrict__ Al,
         const bf16* __restrict__ Bh, const bf16* __restrict__ Bl,
         const float* __restrict__ Res, float* __restrict__ C,
         float scale, int K, int Nglob, size_t sA, size_t sB, size_t sC)
{
    extern __shared__ char dsm[];
    const uint32_t sbase = (uint32_t)__cvta_generic_to_shared(dsm);
    const int tid = threadIdx.x, wid = tid >> 5, lane = tid & 31;
    const int b = blockIdx.z, m0 = blockIdx.y * 128, n0 = blockIdx.x * 128;
    const int wm = wid & 1, wn = wid >> 1;          // warp tile 64(M) x 32(N)

    const bf16* pAh = Ah + (size_t)b * sA;
    const bf16* pAl = Al + (size_t)b * sA;
    const bf16* pBh = Bh + (size_t)b * sB;
    const bf16* pBl = Bl + (size_t)b * sB;

    const int KT = K >> 5;

    // cp.async mapping: 2048 16B chunks/stage, 8 per thread.
    auto load = [&](int kc, int s) {
        uint32_t st = sbase + s * STAGE;
#pragma unroll
        for (int t = 0; t < 8; t++) {
            int idx = t * 256 + tid;
            int reg = idx >> 10;               // 0 = A, 1 = B
            int ch  = idx & 1023;
            int row = ch >> 3, c = ch & 7;
            int plane = c >> 2, cc = c & 3;    // hi chunks 0-3, lo chunks 4-7
            const bf16* src = reg ? (plane ? pBl : pBh) : (plane ? pAl : pAh);
            int rbase = reg ? n0 : m0;
            uint32_t dst = st + (uint32_t)(reg * BOFF + row * 128 + ((c ^ (row & 7)) * 16));
            cp16(dst, (const char*)src + ((size_t)(rbase + row) * K + kc * 32 + cc * 8) * 2);
        }
        cp_commit();
    };

    float acc[4][4][4];
#pragma unroll
    for (int mi = 0; mi < 4; mi++)
#pragma unroll
        for (int ni = 0; ni < 4; ni++)
#pragma unroll
            for (int j = 0; j < 4; j++) acc[mi][ni][j] = 0.f;

    // ldmatrix lane geometry
    const int rowa = wm * 64 + (lane & 15);
    const int ka   = lane >> 4;                // 0/1 -> chunk within k16 step
    const int xa   = rowa & 7;
    const int rowb = wn * 32 + (lane & 7) + ((lane >> 4) << 3);
    const int kb   = (lane >> 3) & 1;
    const int xb   = rowb & 7;

    auto compute = [&](int s) {
        uint32_t st = sbase + s * STAGE;
#pragma unroll
        for (int ks = 0; ks < 2; ks++) {
            uint32_t ah[4][4], al[4][4], bh[2][4], bl[2][4];
#pragma unroll
            for (int mi = 0; mi < 4; mi++) {
                uint32_t rb = st + (uint32_t)((rowa + mi * 16) * 128);
                ldsm4(ah[mi], rb + (uint32_t)(((2 * ks + ka) ^ xa) * 16));
                ldsm4(al[mi], rb + (uint32_t)(((4 + 2 * ks + ka) ^ xa) * 16));
            }
#pragma unroll
            for (int j = 0; j < 2; j++) {
                uint32_t rb = st + BOFF + (uint32_t)((rowb + j * 16) * 128);
                ldsm4(bh[j], rb + (uint32_t)(((2 * ks + kb) ^ xb) * 16));
                ldsm4(bl[j], rb + (uint32_t)(((4 + 2 * ks + kb) ^ xb) * 16));
            }
            // pass-major: 16 independent MMAs per pass (chain gap = 16)
#pragma unroll
            for (int mi = 0; mi < 4; mi++)
#pragma unroll
                for (int j = 0; j < 2; j++) {
                    mma16816(acc[mi][2 * j],     ah[mi], bh[j]);
                    mma16816(acc[mi][2 * j + 1], ah[mi], bh[j] + 2);
                }
#pragma unroll
            for (int mi = 0; mi < 4; mi++)
#pragma unroll
                for (int j = 0; j < 2; j++) {
                    mma16816(acc[mi][2 * j],     al[mi], bh[j]);
                    mma16816(acc[mi][2 * j + 1], al[mi], bh[j] + 2);
                }
#pragma unroll
            for (int mi = 0; mi < 4; mi++)
#pragma unroll
                for (int j = 0; j < 2; j++) {
                    mma16816(acc[mi][2 * j],     ah[mi], bl[j]);
                    mma16816(acc[mi][2 * j + 1], ah[mi], bl[j] + 2);
                }
        }
    };

    load(0, 0);
    if (KT > 1) load(1, 1);

    for (int ci = 0; ci < KT; ci++) {
        if (ci < KT - 1) cp_wait<1>(); else cp_wait<0>();
        __syncthreads();
        if (ci + 2 < KT) load(ci + 2, (ci + 2) % 3);
        compute(ci % 3);
    }

    // epilogue
    float* Co = C + (size_t)b * sC;
    const float* Rp = ADD ? (Res + (size_t)b * sC) : nullptr;
    const int rbase = m0 + wm * 64 + (lane >> 2);
    const int cbase = n0 + wn * 32 + (lane & 3) * 2;
#pragma unroll
    for (int mi = 0; mi < 4; mi++) {
#pragma unroll
        for (int ni = 0; ni < 4; ni++) {
#pragma unroll
            for (int h = 0; h < 2; h++) {
                int r = rbase + mi * 16 + h * 8;
                int c = cbase + ni * 8;
                float2 v;
                v.x = acc[mi][ni][2 * h]     * scale;
                v.y = acc[mi][ni][2 * h + 1] * scale;
                size_t go = (size_t)r * Nglob + c;
                if (ADD) {
                    float2 d = *(const float2*)(Rp + go);
                    v.x += d.x; v.y += d.y;
                }
                *(float2*)(Co + go) = v;
            }
        }
    }
}

// ---------------- fused conversion kernels ----------------
__global__ void stx_k(const float* __restrict__ in, bf16* __restrict__ oh,
                      bf16* __restrict__ ol, bf16* __restrict__ ohT,
                      bf16* __restrict__ olT, int R, int Cc)
{
    __shared__ float t[32][33];
    int b = blockIdx.z;
    int c0 = blockIdx.x * 32, r0 = blockIdx.y * 32;
    const float* ip = in + (size_t)b * R * Cc;
    size_t nb = (size_t)b * R * Cc;
    int tx = threadIdx.x, ty = threadIdx.y;
#pragma unroll
    for (int i = 0; i < 4; i++) {
        int r = r0 + ty + i * 8;
        float v = ip[(size_t)r * Cc + c0 + tx];
        t[ty + i * 8][tx] = v;
        bf16 h, l;
        split1(v, h, l);
        oh[nb + (size_t)r * Cc + c0 + tx] = h;
        ol[nb + (size_t)r * Cc + c0 + tx] = l;
    }
    __syncthreads();
#pragma unroll
    for (int i = 0; i < 4; i++) {
        int c = c0 + ty + i * 8;
        bf16 h, l;
        split1(t[tx][ty + i * 8], h, l);
        ohT[nb + (size_t)c * R + r0 + tx] = h;
        olT[nb + (size_t)c * R + r0 + tx] = l;
    }
}

__global__ void split_k(const float* __restrict__ in, bf16* __restrict__ h,
                        bf16* __restrict__ l, size_t n4)
{
    size_t i = (size_t)blockIdx.x * blockDim.x + threadIdx.x;
    if (i >= n4) return;
    float4 v = ((const float4*)in)[i];
    bf16 h0, l0, h1, l1, h2, l2, h3, l3;
    split1(v.x, h0, l0); split1(v.y, h1, l1); split1(v.z, h2, l2); split1(v.w, h3, l3);
    __nv_bfloat162* hp = (__nv_bfloat162*)h;
    __nv_bfloat162* lp = (__nv_bfloat162*)l;
    hp[i * 2]     = __nv_bfloat162(h0, h1);
    hp[i * 2 + 1] = __nv_bfloat162(h2, h3);
    lp[i * 2]     = __nv_bfloat162(l0, l1);
    lp[i * 2 + 1] = __nv_bfloat162(l2, l3);
}

__global__ void softrow512_k(const float* __restrict__ S, bf16* __restrict__ oh,
                             bf16* __restrict__ ol)
{
    int warp = threadIdx.x >> 5, lane = threadIdx.x & 31;
    size_t row = (size_t)blockIdx.x * 8 + warp;
    const float4* p4 = (const float4*)(S + row * SDIM);
    float4 v[4];
    float m = NEG_INF;
#pragma unroll
    for (int i = 0; i < 4; i++) {
        v[i] = p4[lane + i * 32];
        m = fmaxf(m, fmaxf(fmaxf(v[i].x, v[i].y), fmaxf(v[i].z, v[i].w)));
    }
#pragma unroll
    for (int o = 16; o > 0; o >>= 1) m = fmaxf(m, __shfl_xor_sync(0xffffffffu, m, o));
    float s = 0.f;
#pragma unroll
    for (int i = 0; i < 4; i++)
        s += __expf(v[i].x - m) + __expf(v[i].y - m) + __expf(v[i].z - m) + __expf(v[i].w - m);
#pragma unroll
    for (int o = 16; o > 0; o >>= 1) s += __shfl_xor_sync(0xffffffffu, s, o);
    float inv = __fdividef(1.0f, s);
    __nv_bfloat162* hp = (__nv_bfloat162*)(oh + row * SDIM);
    __nv_bfloat162* lp = (__nv_bfloat162*)(ol + row * SDIM);
#pragma unroll
    for (int i = 0; i < 4; i++) {
        bf16 h0, l0, h1, l1, h2, l2, h3, l3;
        split1(__expf(v[i].x - m) * inv, h0, l0);
        split1(__expf(v[i].y - m) * inv, h1, l1);
        split1(__expf(v[i].z - m) * inv, h2, l2);
        split1(__expf(v[i].w - m) * inv, h3, l3);
        int p = (lane + i * 32) * 2;
        hp[p]     = __nv_bfloat162(h0, h1);
        hp[p + 1] = __nv_bfloat162(h2, h3);
        lp[p]     = __nv_bfloat162(l0, l1);
        lp[p + 1] = __nv_bfloat162(l2, l3);
    }
}

__global__ void softrow4096_k(const float* __restrict__ S, bf16* __restrict__ oh,
                              bf16* __restrict__ ol)
{
    __shared__ float sh[16];
    int tid = threadIdx.x, lane = tid & 31, warp = tid >> 5;
    size_t row = blockIdx.x;
    const float4* p4 = (const float4*)(S + row * TDIM);
    float4 v[2];
    float m = NEG_INF;
#pragma unroll
    for (int i = 0; i < 2; i++) {
        v[i] = p4[tid + i * 512];
        m = fmaxf(m, fmaxf(fmaxf(v[i].x, v[i].y), fmaxf(v[i].z, v[i].w)));
    }
#pragma unroll
    for (int o = 16; o > 0; o >>= 1) m = fmaxf(m, __shfl_xor_sync(0xffffffffu, m, o));
    if (!lane) sh[warp] = m;
    __syncthreads();
    if (tid < 16) {
        float t = sh[tid];
#pragma unroll
        for (int o = 8; o > 0; o >>= 1) t = fmaxf(t, __shfl_xor_sync(0xffffu, t, o));
        if (!tid) sh[0] = t;
    }
    __syncthreads();
    m = sh[0];
    __syncthreads();
    float s = 0.f;
#pragma unroll
    for (int i = 0; i < 2; i++)
        s += __expf(v[i].x - m) + __expf(v[i].y - m) + __expf(v[i].z - m) + __expf(v[i].w - m);
#pragma unroll
    for (int o = 16; o > 0; o >>= 1) s += __shfl_xor_sync(0xffffffffu, s, o);
    if (!lane) sh[warp] = s;
    __syncthreads();
    if (tid < 16) {
        float t = sh[tid];
#pragma unroll
        for (int o = 8; o > 0; o >>= 1) t += __shfl_xor_sync(0xffffu, t, o);
        if (!tid) sh[0] = t;
    }
    __syncthreads();
    float inv = __fdividef(1.0f, sh[0]);
    __nv_bfloat162* hp = (__nv_bfloat162*)(oh + row * TDIM);
    __nv_bfloat162* lp = (__nv_bfloat162*)(ol + row * TDIM);
#pragma unroll
    for (int i = 0; i < 2; i++) {
        bf16 h0, l0, h1, l1, h2, l2, h3, l3;
        split1(__expf(v[i].x - m) * inv, h0, l0);
        split1(__expf(v[i].y - m) * inv, h1, l1);
        split1(__expf(v[i].z - m) * inv, h2, l2);
        split1(__expf(v[i].w - m) * inv, h3, l3);
        int p = (tid + i * 512) * 2;
        hp[p]     = __nv_bfloat162(h0, h1);
        hp[p + 1] = __nv_bfloat162(h2, h3);
        lp[p]     = __nv_bfloat162(l0, l1);
        lp[p + 1] = __nv_bfloat162(l2, l3);
    }
}

// ---------------- column softmax (over T) pipeline ----------------
__global__ void colpart_k(const float* __restrict__ S, float* __restrict__ pm,
                          float* __restrict__ ps)
{
    int b = blockIdx.y, ch = blockIdx.x, s = threadIdx.x;
    const float* p = S + (size_t)b * TDIM * SDIM + (size_t)ch * CHROWS * SDIM + s;
    float m = NEG_INF, sum = 0.f;
    for (int t = 0; t < CHROWS; t++) {
        float v = p[(size_t)t * SDIM];
        float nm = fmaxf(m, v);
        sum = sum * __expf(m - nm) + __expf(v - nm);
        m = nm;
    }
    int o = (b * NCHUNK + ch) * SDIM + s;
    pm[o] = m; ps[o] = sum;
}

__global__ void colcomb_k(const float* __restrict__ pm, const float* __restrict__ ps,
                          float* __restrict__ cm, float* __restrict__ cs)
{
    int b = blockIdx.x, s = threadIdx.x;
    float m = NEG_INF;
#pragma unroll
    for (int c = 0; c < NCHUNK; c++) m = fmaxf(m, pm[(b * NCHUNK + c) * SDIM + s]);
    float sum = 0.f;
#pragma unroll
    for (int c = 0; c < NCHUNK; c++)
        sum += ps[(b * NCHUNK + c) * SDIM + s] * __expf(pm[(b * NCHUNK + c) * SDIM + s] - m);
    cm[b * SDIM + s] = m;
    cs[b * SDIM + s] = sum;
}

__global__ void pcolT_k(const float* __restrict__ sc, const float* __restrict__ cm,
                        const float* __restrict__ cs, bf16* __restrict__ oh,
                        bf16* __restrict__ ol)
{
    __shared__ float t[32][33];
    int b = blockIdx.z;
    int s0 = blockIdx.x * 32, t0 = blockIdx.y * 32;
    const float* ip = sc + (size_t)b * TDIM * SDIM;
    int tx = threadIdx.x, ty = threadIdx.y;
#pragma unroll
    for (int i = 0; i < 4; i++)
        t[ty + i * 8][tx] = ip[(size_t)(t0 + ty + i * 8) * SDIM + s0 + tx];
    __syncthreads();
    size_t ob = (size_t)b * SDIM * TDIM;
#pragma unroll
    for (int i = 0; i < 4; i++) {
        int s = s0 + ty + i * 8;
        float m = cm[b * SDIM + s], inv = __fdividef(1.0f, cs[b * SDIM + s]);
        bf16 h, l;
        split1(__expf(t[tx][ty + i * 8] - m) * inv, h, l);
        oh[ob + (size_t)s * TDIM + t0 + tx] = h;
        ol[ob + (size_t)s * TDIM + t0 + tx] = l;
    }
}

// ---------------- launch ----------------
extern "C" void kernel_launch(void* const* d_in, const int* in_sizes, int n_in,
                              void* d_out, int out_size)
{
    const float* x   = (const float*)d_in[0];
    const float* kin = (const float*)d_in[1];
    const float* vin = (const float*)d_in[2];

    float* att = (float*)d_out;
    float* ktv = att + (size_t)NB * TDIM * CDIM;
    float* vtv = ktv + (size_t)NB * SDIM * CDIM;

    float *sc, *vsc, *pcm, *pcs, *cm, *cs;
    bf16 *Xh, *Xl, *XTh, *XTl, *Kh, *Kl, *Vh, *Vl, *VTh, *VTl;
    bf16 *Ph, *Pl, *P2h, *P2l, *P3h, *P3l;
    cudaGetSymbolAddress((void**)&sc, g_sc);     cudaGetSymbolAddress((void**)&vsc, g_vsc);
    cudaGetSymbolAddress((void**)&pcm, g_pcm);   cudaGetSymbolAddress((void**)&pcs, g_pcs);
    cudaGetSymbolAddress((void**)&cm, g_cm);     cudaGetSymbolAddress((void**)&cs, g_cs);
    cudaGetSymbolAddress((void**)&Xh, g_Xh);     cudaGetSymbolAddress((void**)&Xl, g_Xl);
    cudaGetSymbolAddress((void**)&XTh, g_XTh);   cudaGetSymbolAddress((void**)&XTl, g_XTl);
    cudaGetSymbolAddress((void**)&Kh, g_Kh);     cudaGetSymbolAddress((void**)&Kl, g_Kl);
    cudaGetSymbolAddress((void**)&Vh, g_Vh);     cudaGetSymbolAddress((void**)&Vl, g_Vl);
    cudaGetSymbolAddress((void**)&VTh, g_VTh);   cudaGetSymbolAddress((void**)&VTl, g_VTl);
    cudaGetSymbolAddress((void**)&Ph, g_Ph);     cudaGetSymbolAddress((void**)&Pl, g_Pl);
    cudaGetSymbolAddress((void**)&P2h, g_P2h);   cudaGetSymbolAddress((void**)&P2l, g_P2l);
    cudaGetSymbolAddress((void**)&P3h, g_P3h);   cudaGetSymbolAddress((void**)&P3l, g_P3l);

    const int SMEM = 3 * STAGE;  // 98304
    cudaFuncSetAttribute(mma_gemm<false>, cudaFuncAttributeMaxDynamicSharedMemorySize, SMEM);
    cudaFuncSetAttribute(mma_gemm<true>,  cudaFuncAttributeMaxDynamicSharedMemorySize, SMEM);

    const float scale = 0.03125f;  // 1/sqrt(1024)

    // operand prep
    stx_k<<<dim3(CDIM / 32, TDIM / 32, NB), dim3(32, 8)>>>(x, Xh, Xl, XTh, XTl, TDIM, CDIM);
    {
        size_t n4 = (size_t)NB * SDIM * CDIM / 4;
        split_k<<<(unsigned)((n4 + 255) / 256), 256>>>(kin, Kh, Kl, n4);
    }
    stx_k<<<dim3(CDIM / 32, SDIM / 32, NB), dim3(32, 8)>>>(vin, Vh, Vl, VTh, VTl, SDIM, CDIM);

    // 1) scores = scale * X K^T  [T,S]
    mma_gemm<false><<<dim3(SDIM / 128, TDIM / 128, NB), 256, SMEM>>>(
        Xh, Xl, Kh, Kl, nullptr, sc, scale, CDIM, SDIM,
        (size_t)TDIM * CDIM, (size_t)SDIM * CDIM, (size_t)TDIM * SDIM);

    // softmax conversions
    softrow512_k<<<NB * TDIM / 8, 256>>>(sc, Ph, Pl);
    colpart_k<<<dim3(NCHUNK, NB), 512>>>(sc, pcm, pcs);
    colcomb_k<<<NB, 512>>>(pcm, pcs, cm, cs);
    pcolT_k<<<dim3(SDIM / 32, TDIM / 32, NB), dim3(32, 8)>>>(sc, cm, cs, P2h, P2l);

    // 2) att = P V   (B = V^T [C,S], K=512)
    mma_gemm<false><<<dim3(CDIM / 128, TDIM / 128, NB), 256, SMEM>>>(
        Ph, Pl, VTh, VTl, nullptr, att, 1.0f, SDIM, CDIM,
        (size_t)TDIM * SDIM, (size_t)CDIM * SDIM, (size_t)TDIM * CDIM);

    // 3) k_t = k + P2^T X   (B = X^T [C,T], K=4096)
    mma_gemm<true><<<dim3(CDIM / 128, SDIM / 128, NB), 256, SMEM>>>(
        P2h, P2l, XTh, XTl, kin, ktv, 1.0f, TDIM, CDIM,
        (size_t)SDIM * TDIM, (size_t)CDIM * TDIM, (size_t)SDIM * CDIM);

    // 4) v_scores = scale * V X^T  [S,T]
    mma_gemm<false><<<dim3(TDIM / 128, SDIM / 128, NB), 256, SMEM>>>(
        Vh, Vl, Xh, Xl, nullptr, vsc, scale, CDIM, TDIM,
        (size_t)SDIM * CDIM, (size_t)TDIM * CDIM, (size_t)SDIM * TDIM);

    // P3 (row softmax over 4096)
    softrow4096_k<<<NB * SDIM, 512>>>(vsc, P3h, P3l);

    // 5) v_t = v + P3 X   (B = X^T [C,T], K=4096)
    mma_gemm<true><<<dim3(CDIM / 128, SDIM / 128, NB), 256, SMEM>>>(
        P3h, P3l, XTh, XTl, vin, vtv, 1.0f, TDIM, CDIM,
        (size_t)SDIM * TDIM, (size_t)CDIM * TDIM, (size_t)SDIM * CDIM);
}

// round 6
// speedup vs baseline: 1.3498x; 1.2167x over previous
#include <cuda_runtime.h>
#include <cuda_fp16.h>
#include <cstdint>

#define NB 8
#define TDIM 4096
#define SDIM 512
#define CDIM 1024
#define NCHUNK 16
#define CHROWS (TDIM / NCHUNK)
#define NEG_INF (-3.0e38f)

typedef __half hf;

// ---------------- scratch (static device globals; no allocation) ----------------
__device__ float g_sc [(size_t)NB * TDIM * SDIM];
__device__ float g_vsc[(size_t)NB * SDIM * TDIM];
__device__ __align__(16) hf g_Xh [(size_t)NB * TDIM * CDIM], g_Xl [(size_t)NB * TDIM * CDIM];
__device__ __align__(16) hf g_XTh[(size_t)NB * CDIM * TDIM], g_XTl[(size_t)NB * CDIM * TDIM];
__device__ __align__(16) hf g_Kh [(size_t)NB * SDIM * CDIM], g_Kl [(size_t)NB * SDIM * CDIM];
__device__ __align__(16) hf g_Vh [(size_t)NB * SDIM * CDIM], g_Vl [(size_t)NB * SDIM * CDIM];
__device__ __align__(16) hf g_VTh[(size_t)NB * CDIM * SDIM], g_VTl[(size_t)NB * CDIM * SDIM];
__device__ __align__(16) hf g_Ph [(size_t)NB * TDIM * SDIM], g_Pl [(size_t)NB * TDIM * SDIM];
__device__ __align__(16) hf g_P2h[(size_t)NB * SDIM * TDIM], g_P2l[(size_t)NB * SDIM * TDIM];
__device__ __align__(16) hf g_P3h[(size_t)NB * SDIM * TDIM], g_P3l[(size_t)NB * SDIM * TDIM];
__device__ float g_pcm[NB * NCHUNK * SDIM], g_pcs[NB * NCHUNK * SDIM];
__device__ float g_cm [NB * SDIM], g_cs [NB * SDIM];

// ---------------- PTX helpers ----------------
__device__ __forceinline__ void cp16(uint32_t dst, const void* src) {
    asm volatile("cp.async.cg.shared.global [%0], [%1], 16;" :: "r"(dst), "l"(src));
}
__device__ __forceinline__ void cp_commit() {
    asm volatile("cp.async.commit_group;" ::: "memory");
}
template <int N>
__device__ __forceinline__ void cp_wait() {
    asm volatile("cp.async.wait_group %0;" :: "n"(N) : "memory");
}
__device__ __forceinline__ void ldsm4(uint32_t* r, uint32_t addr) {
    asm volatile("ldmatrix.sync.aligned.m8n8.x4.shared.b16 {%0,%1,%2,%3}, [%4];"
                 : "=r"(r[0]), "=r"(r[1]), "=r"(r[2]), "=r"(r[3]) : "r"(addr));
}
__device__ __forceinline__ void mma16816(float* d, const uint32_t* a, const uint32_t* b) {
    asm volatile(
        "mma.sync.aligned.m16n8k16.row.col.f32.f16.f16.f32 "
        "{%0,%1,%2,%3}, {%4,%5,%6,%7}, {%8,%9}, {%0,%1,%2,%3};"
        : "+f"(d[0]), "+f"(d[1]), "+f"(d[2]), "+f"(d[3])
        : "r"(a[0]), "r"(a[1]), "r"(a[2]), "r"(a[3]), "r"(b[0]), "r"(b[1]));
}
__device__ __forceinline__ void split1(float f, hf& h, hf& l) {
    h = __float2half_rn(f);
    l = __float2half_rn(f - __half2float(h));
}

// ---------------------------------------------------------------------------
// fp16 emulated-fp32 GEMM on HMMA. Tile 128x128, BK=32, 256 thr, 8 warps
// (warp tile 64x32). PASSES=3: Ah*Bh + Al*Bh + Ah*Bl (scores-grade).
// PASSES=2: Ah*Bh + Al*Bh (B single fp16; B-lo never loaded).
// SMEM: hi|lo planes packed in 128B SW128 rows; 3 stages x 32KB, 2 CTAs/SM.
// ---------------------------------------------------------------------------
#define STAGE 32768
#define BOFF  16384

template <int PASSES, bool ADD>
__global__ void __launch_bounds__(256, 2)
mma_gemm(const hf* __restrict__ Ah, const hf* __restrict__ Al,
         const hf* __restrict__ Bh, const hf* __restrict__ Bl,
         const float* __restrict__ Res, float* __restrict__ C,
         float scale, int K, int Nglob, size_t sA, size_t sB, size_t sC)
{
    extern __shared__ char dsm[];
    const uint32_t sbase = (uint32_t)__cvta_generic_to_shared(dsm);
    const int tid = threadIdx.x, wid = tid >> 5, lane = tid & 31;
    const int b = blockIdx.z, m0 = blockIdx.y * 128, n0 = blockIdx.x * 128;
    const int wm = wid & 1, wn = wid >> 1;

    const hf* pAh = Ah + (size_t)b * sA;
    const hf* pAl = Al + (size_t)b * sA;
    const hf* pBh = Bh + (size_t)b * sB;
    const hf* pBl = (PASSES == 3) ? (Bl + (size_t)b * sB) : nullptr;

    const int KT = K >> 5;

    auto load = [&](int kc, int s) {
        uint32_t st = sbase + s * STAGE;
#pragma unroll
        for (int t = 0; t < 8; t++) {
            int idx = t * 256 + tid;
            int reg = idx >> 10;               // 0 = A, 1 = B
            int ch  = idx & 1023;
            int row = ch >> 3, c = ch & 7;
            int plane = c >> 2, cc = c & 3;    // hi chunks 0-3, lo chunks 4-7
            if (PASSES == 2 && reg == 1 && plane == 1) continue;  // skip B-lo
            const hf* src = reg ? (plane ? pBl : pBh) : (plane ? pAl : pAh);
            int rbase = reg ? n0 : m0;
            uint32_t dst = st + (uint32_t)(reg * BOFF + row * 128 + ((c ^ (row & 7)) * 16));
            cp16(dst, (const char*)src + ((size_t)(rbase + row) * K + kc * 32 + cc * 8) * 2);
        }
        cp_commit();
    };

    float acc[4][4][4];
#pragma unroll
    for (int mi = 0; mi < 4; mi++)
#pragma unroll
        for (int ni = 0; ni < 4; ni++)
#pragma unroll
            for (int j = 0; j < 4; j++) acc[mi][ni][j] = 0.f;

    const int rowa = wm * 64 + (lane & 15);
    const int ka   = lane >> 4;
    const int xa   = rowa & 7;
    const int rowb = wn * 32 + (lane & 7) + ((lane >> 4) << 3);
    const int kb   = (lane >> 3) & 1;
    const int xb   = rowb & 7;

    auto compute = [&](int s) {
        uint32_t st = sbase + s * STAGE;
#pragma unroll
        for (int ks = 0; ks < 2; ks++) {
            uint32_t ah[4][4], al[4][4], bh[2][4], bl[2][4];
#pragma unroll
            for (int mi = 0; mi < 4; mi++) {
                uint32_t rb = st + (uint32_t)((rowa + mi * 16) * 128);
                ldsm4(ah[mi], rb + (uint32_t)(((2 * ks + ka) ^ xa) * 16));
                ldsm4(al[mi], rb + (uint32_t)(((4 + 2 * ks + ka) ^ xa) * 16));
            }
#pragma unroll
            for (int j = 0; j < 2; j++) {
                uint32_t rb = st + BOFF + (uint32_t)((rowb + j * 16) * 128);
                ldsm4(bh[j], rb + (uint32_t)(((2 * ks + kb) ^ xb) * 16));
                if (PASSES == 3)
                    ldsm4(bl[j], rb + (uint32_t)(((4 + 2 * ks + kb) ^ xb) * 16));
            }
#pragma unroll
            for (int mi = 0; mi < 4; mi++)
#pragma unroll
                for (int j = 0; j < 2; j++) {
                    mma16816(acc[mi][2 * j],     ah[mi], bh[j]);
                    mma16816(acc[mi][2 * j + 1], ah[mi], bh[j] + 2);
                }
#pragma unroll
            for (int mi = 0; mi < 4; mi++)
#pragma unroll
                for (int j = 0; j < 2; j++) {
                    mma16816(acc[mi][2 * j],     al[mi], bh[j]);
                    mma16816(acc[mi][2 * j + 1], al[mi], bh[j] + 2);
                }
            if (PASSES == 3) {
#pragma unroll
                for (int mi = 0; mi < 4; mi++)
#pragma unroll
                    for (int j = 0; j < 2; j++) {
                        mma16816(acc[mi][2 * j],     ah[mi], bl[j]);
                        mma16816(acc[mi][2 * j + 1], ah[mi], bl[j] + 2);
                    }
            }
        }
    };

    load(0, 0);
    if (KT > 1) load(1, 1);

    for (int ci = 0; ci < KT; ci++) {
        if (ci < KT - 1) cp_wait<1>(); else cp_wait<0>();
        __syncthreads();
        if (ci + 2 < KT) load(ci + 2, (ci + 2) % 3);
        compute(ci % 3);
    }

    float* Co = C + (size_t)b * sC;
    const float* Rp = ADD ? (Res + (size_t)b * sC) : nullptr;
    const int rbase = m0 + wm * 64 + (lane >> 2);
    const int cbase = n0 + wn * 32 + (lane & 3) * 2;
#pragma unroll
    for (int mi = 0; mi < 4; mi++) {
#pragma unroll
        for (int ni = 0; ni < 4; ni++) {
#pragma unroll
            for (int h = 0; h < 2; h++) {
                int r = rbase + mi * 16 + h * 8;
                int c = cbase + ni * 8;
                float2 v;
                v.x = acc[mi][ni][2 * h]     * scale;
                v.y = acc[mi][ni][2 * h + 1] * scale;
                size_t go = (size_t)r * Nglob + c;
                if (ADD) {
                    float2 d = *(const float2*)(Rp + go);
                    v.x += d.x; v.y += d.y;
                }
                *(float2*)(Co + go) = v;
            }
        }
    }
}

// ---------------- fused conversion kernels ----------------
__global__ void stx_k(const float* __restrict__ in, hf* __restrict__ oh,
                      hf* __restrict__ ol, hf* __restrict__ ohT,
                      hf* __restrict__ olT, int R, int Cc)
{
    __shared__ float t[32][33];
    int b = blockIdx.z;
    int c0 = blockIdx.x * 32, r0 = blockIdx.y * 32;
    const float* ip = in + (size_t)b * R * Cc;
    size_t nb = (size_t)b * R * Cc;
    int tx = threadIdx.x, ty = threadIdx.y;
#pragma unroll
    for (int i = 0; i < 4; i++) {
        int r = r0 + ty + i * 8;
        float v = ip[(size_t)r * Cc + c0 + tx];
        t[ty + i * 8][tx] = v;
        hf h, l;
        split1(v, h, l);
        oh[nb + (size_t)r * Cc + c0 + tx] = h;
        ol[nb + (size_t)r * Cc + c0 + tx] = l;
    }
    __syncthreads();
#pragma unroll
    for (int i = 0; i < 4; i++) {
        int c = c0 + ty + i * 8;
        hf h, l;
        split1(t[tx][ty + i * 8], h, l);
        ohT[nb + (size_t)c * R + r0 + tx] = h;
        olT[nb + (size_t)c * R + r0 + tx] = l;
    }
}

__global__ void split_k(const float* __restrict__ in, hf* __restrict__ h,
                        hf* __restrict__ l, size_t n4)
{
    size_t i = (size_t)blockIdx.x * blockDim.x + threadIdx.x;
    if (i >= n4) return;
    float4 v = ((const float4*)in)[i];
    hf h0, l0, h1, l1, h2, l2, h3, l3;
    split1(v.x, h0, l0); split1(v.y, h1, l1); split1(v.z, h2, l2); split1(v.w, h3, l3);
    __half2* hp = (__half2*)h;
    __half2* lp = (__half2*)l;
    hp[i * 2]     = __halves2half2(h0, h1);
    hp[i * 2 + 1] = __halves2half2(h2, h3);
    lp[i * 2]     = __halves2half2(l0, l1);
    lp[i * 2 + 1] = __halves2half2(l2, l3);
}

__global__ void softrow512_k(const float* __restrict__ S, hf* __restrict__ oh,
                             hf* __restrict__ ol)
{
    int warp = threadIdx.x >> 5, lane = threadIdx.x & 31;
    size_t row = (size_t)blockIdx.x * 8 + warp;
    const float4* p4 = (const float4*)(S + row * SDIM);
    float4 v[4];
    float m = NEG_INF;
#pragma unroll
    for (int i = 0; i < 4; i++) {
        v[i] = p4[lane + i * 32];
        m = fmaxf(m, fmaxf(fmaxf(v[i].x, v[i].y), fmaxf(v[i].z, v[i].w)));
    }
#pragma unroll
    for (int o = 16; o > 0; o >>= 1) m = fmaxf(m, __shfl_xor_sync(0xffffffffu, m, o));
    float s = 0.f;
#pragma unroll
    for (int i = 0; i < 4; i++)
        s += __expf(v[i].x - m) + __expf(v[i].y - m) + __expf(v[i].z - m) + __expf(v[i].w - m);
#pragma unroll
    for (int o = 16; o > 0; o >>= 1) s += __shfl_xor_sync(0xffffffffu, s, o);
    float inv = __fdividef(1.0f, s);
    __half2* hp = (__half2*)(oh + row * SDIM);
    __half2* lp = (__half2*)(ol + row * SDIM);
#pragma unroll
    for (int i = 0; i < 4; i++) {
        hf h0, l0, h1, l1, h2, l2, h3, l3;
        split1(__expf(v[i].x - m) * inv, h0, l0);
        split1(__expf(v[i].y - m) * inv, h1, l1);
        split1(__expf(v[i].z - m) * inv, h2, l2);
        split1(__expf(v[i].w - m) * inv, h3, l3);
        int p = (lane + i * 32) * 2;
        hp[p]     = __halves2half2(h0, h1);
        hp[p + 1] = __halves2half2(h2, h3);
        lp[p]     = __halves2half2(l0, l1);
        lp[p + 1] = __halves2half2(l2, l3);
    }
}

__global__ void softrow4096_k(const float* __restrict__ S, hf* __restrict__ oh,
                              hf* __restrict__ ol)
{
    __shared__ float sh[16];
    int tid = threadIdx.x, lane = tid & 31, warp = tid >> 5;
    size_t row = blockIdx.x;
    const float4* p4 = (const float4*)(S + row * TDIM);
    float4 v[2];
    float m = NEG_INF;
#pragma unroll
    for (int i = 0; i < 2; i++) {
        v[i] = p4[tid + i * 512];
        m = fmaxf(m, fmaxf(fmaxf(v[i].x, v[i].y), fmaxf(v[i].z, v[i].w)));
    }
#pragma unroll
    for (int o = 16; o > 0; o >>= 1) m = fmaxf(m, __shfl_xor_sync(0xffffffffu, m, o));
    if (!lane) sh[warp] = m;
    __syncthreads();
    if (tid < 16) {
        float t = sh[tid];
#pragma unroll
        for (int o = 8; o > 0; o >>= 1) t = fmaxf(t, __shfl_xor_sync(0xffffu, t, o));
        if (!tid) sh[0] = t;
    }
    __syncthreads();
    m = sh[0];
    __syncthreads();
    float s = 0.f;
#pragma unroll
    for (int i = 0; i < 2; i++)
        s += __expf(v[i].x - m) + __expf(v[i].y - m) + __expf(v[i].z - m) + __expf(v[i].w - m);
#pragma unroll
    for (int o = 16; o > 0; o >>= 1) s += __shfl_xor_sync(0xffffffffu, s, o);
    if (!lane) sh[warp] = s;
    __syncthreads();
    if (tid < 16) {
        float t = sh[tid];
#pragma unroll
        for (int o = 8; o > 0; o >>= 1) t += __shfl_xor_sync(0xffffu, t, o);
        if (!tid) sh[0] = t;
    }
    __syncthreads();
    float inv = __fdividef(1.0f, sh[0]);
    __half2* hp = (__half2*)(oh + row * TDIM);
    __half2* lp = (__half2*)(ol + row * TDIM);
#pragma unroll
    for (int i = 0; i < 2; i++) {
        hf h0, l0, h1, l1, h2, l2, h3, l3;
        split1(__expf(v[i].x - m) * inv, h0, l0);
        split1(__expf(v[i].y - m) * inv, h1, l1);
        split1(__expf(v[i].z - m) * inv, h2, l2);
        split1(__expf(v[i].w - m) * inv, h3, l3);
        int p = (tid + i * 512) * 2;
        hp[p]     = __halves2half2(h0, h1);
        hp[p + 1] = __halves2half2(h2, h3);
        lp[p]     = __halves2half2(l0, l1);
        lp[p + 1] = __halves2half2(l2, l3);
    }
}

// ---------------- column softmax (over T) pipeline ----------------
__global__ void colpart_k(const float* __restrict__ S, float* __restrict__ pm,
                          float* __restrict__ ps)
{
    int b = blockIdx.y, ch = blockIdx.x, s = threadIdx.x;
    const float* p = S + (size_t)b * TDIM * SDIM + (size_t)ch * CHROWS * SDIM + s;
    float m = NEG_INF, sum = 0.f;
    for (int t = 0; t < CHROWS; t++) {
        float v = p[(size_t)t * SDIM];
        float nm = fmaxf(m, v);
        sum = sum * __expf(m - nm) + __expf(v - nm);
        m = nm;
    }
    int o = (b * NCHUNK + ch) * SDIM + s;
    pm[o] = m; ps[o] = sum;
}

__global__ void colcomb_k(const float* __restrict__ pm, const float* __restrict__ ps,
                          float* __restrict__ cm, float* __restrict__ cs)
{
    int b = blockIdx.x, s = threadIdx.x;
    float m = NEG_INF;
#pragma unroll
    for (int c = 0; c < NCHUNK; c++) m = fmaxf(m, pm[(b * NCHUNK + c) * SDIM + s]);
    float sum = 0.f;
#pragma unroll
    for (int c = 0; c < NCHUNK; c++)
        sum += ps[(b * NCHUNK + c) * SDIM + s] * __expf(pm[(b * NCHUNK + c) * SDIM + s] - m);
    cm[b * SDIM + s] = m;
    cs[b * SDIM + s] = sum;
}

__global__ void pcolT_k(const float* __restrict__ sc, const float* __restrict__ cm,
                        const float* __restrict__ cs, hf* __restrict__ oh,
                        hf* __restrict__ ol)
{
    __shared__ float t[32][33];
    int b = blockIdx.z;
    int s0 = blockIdx.x * 32, t0 = blockIdx.y * 32;
    const float* ip = sc + (size_t)b * TDIM * SDIM;
    int tx = threadIdx.x, ty = threadIdx.y;
#pragma unroll
    for (int i = 0; i < 4; i++)
        t[ty + i * 8][tx] = ip[(size_t)(t0 + ty + i * 8) * SDIM + s0 + tx];
    __syncthreads();
    size_t ob = (size_t)b * SDIM * TDIM;
#pragma unroll
    for (int i = 0; i < 4; i++) {
        int s = s0 + ty + i * 8;
        float m = cm[b * SDIM + s], inv = __fdividef(1.0f, cs[b * SDIM + s]);
        hf h, l;
        split1(__expf(t[tx][ty + i * 8] - m) * inv, h, l);
        oh[ob + (size_t)s * TDIM + t0 + tx] = h;
        ol[ob + (size_t)s * TDIM + t0 + tx] = l;
    }
}

// ---------------- launch ----------------
extern "C" void kernel_launch(void* const* d_in, const int* in_sizes, int n_in,
                              void* d_out, int out_size)
{
    const float* x   = (const float*)d_in[0];
    const float* kin = (const float*)d_in[1];
    const float* vin = (const float*)d_in[2];

    float* att = (float*)d_out;
    float* ktv = att + (size_t)NB * TDIM * CDIM;
    float* vtv = ktv + (size_t)NB * SDIM * CDIM;

    float *sc, *vsc, *pcm, *pcs, *cm, *cs;
    hf *Xh, *Xl, *XTh, *XTl, *Kh, *Kl, *Vh, *Vl, *VTh, *VTl;
    hf *Ph, *Pl, *P2h, *P2l, *P3h, *P3l;
    cudaGetSymbolAddress((void**)&sc, g_sc);     cudaGetSymbolAddress((void**)&vsc, g_vsc);
    cudaGetSymbolAddress((void**)&pcm, g_pcm);   cudaGetSymbolAddress((void**)&pcs, g_pcs);
    cudaGetSymbolAddress((void**)&cm, g_cm);     cudaGetSymbolAddress((void**)&cs, g_cs);
    cudaGetSymbolAddress((void**)&Xh, g_Xh);     cudaGetSymbolAddress((void**)&Xl, g_Xl);
    cudaGetSymbolAddress((void**)&XTh, g_XTh);   cudaGetSymbolAddress((void**)&XTl, g_XTl);
    cudaGetSymbolAddress((void**)&Kh, g_Kh);     cudaGetSymbolAddress((void**)&Kl, g_Kl);
    cudaGetSymbolAddress((void**)&Vh, g_Vh);     cudaGetSymbolAddress((void**)&Vl, g_Vl);
    cudaGetSymbolAddress((void**)&VTh, g_VTh);   cudaGetSymbolAddress((void**)&VTl, g_VTl);
    cudaGetSymbolAddress((void**)&Ph, g_Ph);     cudaGetSymbolAddress((void**)&Pl, g_Pl);
    cudaGetSymbolAddress((void**)&P2h, g_P2h);   cudaGetSymbolAddress((void**)&P2l, g_P2l);
    cudaGetSymbolAddress((void**)&P3h, g_P3h);   cudaGetSymbolAddress((void**)&P3l, g_P3l);

    const int SMEM = 3 * STAGE;  // 98304
    cudaFuncSetAttribute(mma_gemm<3, false>, cudaFuncAttributeMaxDynamicSharedMemorySize, SMEM);
    cudaFuncSetAttribute(mma_gemm<2, false>, cudaFuncAttributeMaxDynamicSharedMemorySize, SMEM);
    cudaFuncSetAttribute(mma_gemm<2, true>,  cudaFuncAttributeMaxDynamicSharedMemorySize, SMEM);

    const float scale = 0.03125f;  // 1/sqrt(1024)

    // operand prep
    stx_k<<<dim3(CDIM / 32, TDIM / 32, NB), dim3(32, 8)>>>(x, Xh, Xl, XTh, XTl, TDIM, CDIM);
    {
        size_t n4 = (size_t)NB * SDIM * CDIM / 4;
        split_k<<<(unsigned)((n4 + 255) / 256), 256>>>(kin, Kh, Kl, n4);
    }
    stx_k<<<dim3(CDIM / 32, SDIM / 32, NB), dim3(32, 8)>>>(vin, Vh, Vl, VTh, VTl, SDIM, CDIM);

    // 1) scores = scale * X K^T  [T,S]  (3-pass: feeds exp)
    mma_gemm<3, false><<<dim3(SDIM / 128, TDIM / 128, NB), 256, SMEM>>>(
        Xh, Xl, Kh, Kl, nullptr, sc, scale, CDIM, SDIM,
        (size_t)TDIM * CDIM, (size_t)SDIM * CDIM, (size_t)TDIM * SDIM);

    // softmax conversions
    softrow512_k<<<NB * TDIM / 8, 256>>>(sc, Ph, Pl);
    colpart_k<<<dim3(NCHUNK, NB), 512>>>(sc, pcm, pcs);
    colcomb_k<<<NB, 512>>>(pcm, pcs, cm, cs);
    pcolT_k<<<dim3(SDIM / 32, TDIM / 32, NB), dim3(32, 8)>>>(sc, cm, cs, P2h, P2l);

    // 2) att = P V   (2-pass; B = V^T hi only, K=512)
    mma_gemm<2, false><<<dim3(CDIM / 128, TDIM / 128, NB), 256, SMEM>>>(
        Ph, Pl, VTh, VTl, nullptr, att, 1.0f, SDIM, CDIM,
        (size_t)TDIM * SDIM, (size_t)CDIM * SDIM, (size_t)TDIM * CDIM);

    // 3) k_t = k + P2^T X   (2-pass; B = X^T hi only, K=4096)
    mma_gemm<2, true><<<dim3(CDIM / 128, SDIM / 128, NB), 256, SMEM>>>(
        P2h, P2l, XTh, XTl, kin, ktv, 1.0f, TDIM, CDIM,
        (size_t)SDIM * TDIM, (size_t)CDIM * TDIM, (size_t)SDIM * CDIM);

    // 4) v_scores = scale * V X^T  [S,T]  (3-pass: feeds exp)
    mma_gemm<3, false><<<dim3(TDIM / 128, SDIM / 128, NB), 256, SMEM>>>(
        Vh, Vl, Xh, Xl, nullptr, vsc, scale, CDIM, TDIM,
        (size_t)SDIM * CDIM, (size_t)TDIM * CDIM, (size_t)SDIM * TDIM);

    // P3 (row softmax over 4096)
    softrow4096_k<<<NB * SDIM, 512>>>(vsc, P3h, P3l);

    // 5) v_t = v + P3 X   (2-pass; B = X^T hi only, K=4096)
    mma_gemm<2, true><<<dim3(CDIM / 128, SDIM / 128, NB), 256, SMEM>>>(
        P3h, P3l, XTh, XTl, vin, vtv, 1.0f, TDIM, CDIM,
        (size_t)SDIM * TDIM, (size_t)CDIM * TDIM, (size_t)SDIM * CDIM);
}

// round 7
// speedup vs baseline: 1.5591x; 1.1551x over previous
#include <cuda_runtime.h>
#include <cuda_fp16.h>
#include <cstdint>

#define NB 8
#define TDIM 4096
#define SDIM 512
#define CDIM 1024
#define NCHUNK 16
#define CHROWS (TDIM / NCHUNK)
#define NEG_INF (-3.0e38f)

typedef __half hf;

// ---------------- scratch (static device globals; no allocation) ----------------
__device__ float g_sc [(size_t)NB * TDIM * SDIM];
__device__ float g_vsc[(size_t)NB * SDIM * TDIM];
__device__ __align__(16) hf g_Xh [(size_t)NB * TDIM * CDIM], g_Xl [(size_t)NB * TDIM * CDIM];
__device__ __align__(16) hf g_XTh[(size_t)NB * CDIM * TDIM];
__device__ __align__(16) hf g_Kh [(size_t)NB * SDIM * CDIM];
__device__ __align__(16) hf g_Vh [(size_t)NB * SDIM * CDIM], g_Vl [(size_t)NB * SDIM * CDIM];
__device__ __align__(16) hf g_VTh[(size_t)NB * CDIM * SDIM];
__device__ __align__(16) hf g_Ph [(size_t)NB * TDIM * SDIM], g_Pl [(size_t)NB * TDIM * SDIM];
__device__ __align__(16) hf g_P2h[(size_t)NB * SDIM * TDIM], g_P2l[(size_t)NB * SDIM * TDIM];
__device__ __align__(16) hf g_P3h[(size_t)NB * SDIM * TDIM], g_P3l[(size_t)NB * SDIM * TDIM];
__device__ float g_pcm[NB * NCHUNK * SDIM], g_pcs[NB * NCHUNK * SDIM];
__device__ float g_cm [NB * SDIM], g_cs [NB * SDIM];

// ---------------- PTX helpers ----------------
__device__ __forceinline__ void cp16(uint32_t dst, const void* src) {
    asm volatile("cp.async.cg.shared.global [%0], [%1], 16;" :: "r"(dst), "l"(src));
}
__device__ __forceinline__ void cp_commit() {
    asm volatile("cp.async.commit_group;" ::: "memory");
}
template <int N>
__device__ __forceinline__ void cp_wait() {
    asm volatile("cp.async.wait_group %0;" :: "n"(N) : "memory");
}
__device__ __forceinline__ void ldsm4(uint32_t* r, uint32_t addr) {
    asm volatile("ldmatrix.sync.aligned.m8n8.x4.shared.b16 {%0,%1,%2,%3}, [%4];"
                 : "=r"(r[0]), "=r"(r[1]), "=r"(r[2]), "=r"(r[3]) : "r"(addr));
}
__device__ __forceinline__ void mma16816(float* d, const uint32_t* a, const uint32_t* b) {
    asm volatile(
        "mma.sync.aligned.m16n8k16.row.col.f32.f16.f16.f32 "
        "{%0,%1,%2,%3}, {%4,%5,%6,%7}, {%8,%9}, {%0,%1,%2,%3};"
        : "+f"(d[0]), "+f"(d[1]), "+f"(d[2]), "+f"(d[3])
        : "r"(a[0]), "r"(a[1]), "r"(a[2]), "r"(a[3]), "r"(b[0]), "r"(b[1]));
}
__device__ __forceinline__ void split1(float f, hf& h, hf& l) {
    h = __float2half_rn(f);
    l = __float2half_rn(f - __half2float(h));
}

// ---------------------------------------------------------------------------
// fp16 2-pass emulated GEMM on HMMA: D = Ah*Bh + Al*Bh (B single fp16).
// Tile 128x128, BK=32, 256 thr, warp tile 64x32; 3-stage cp.async, 2 CTAs/SM.
// ---------------------------------------------------------------------------
#define STAGE 32768
#define BOFF  16384

template <bool ADD>
__global__ void __launch_bounds__(256, 2)
mma_gemm(const hf* __restrict__ Ah, const hf* __restrict__ Al,
         const hf* __restrict__ Bh,
         const float* __restrict__ Res, float* __restrict__ C,
         float scale, int K, int Nglob, size_t sA, size_t sB, size_t sC)
{
    extern __shared__ char dsm[];
    const uint32_t sbase = (uint32_t)__cvta_generic_to_shared(dsm);
    const int tid = threadIdx.x, wid = tid >> 5, lane = tid & 31;
    const int b = blockIdx.z, m0 = blockIdx.y * 128, n0 = blockIdx.x * 128;
    const int wm = wid & 1, wn = wid >> 1;

    const hf* pAh = Ah + (size_t)b * sA;
    const hf* pAl = Al + (size_t)b * sA;
    const hf* pBh = Bh + (size_t)b * sB;

    const int KT = K >> 5;

    auto load = [&](int kc, int s) {
        uint32_t st = sbase + s * STAGE;
#pragma unroll
        for (int t = 0; t < 8; t++) {
            int idx = t * 256 + tid;
            int reg = idx >> 10;               // 0 = A, 1 = B
            int ch  = idx & 1023;
            int row = ch >> 3, c = ch & 7;
            int plane = c >> 2, cc = c & 3;    // hi chunks 0-3, lo chunks 4-7
            if (reg == 1 && plane == 1) continue;    // no B-lo
            const hf* src = reg ? pBh : (plane ? pAl : pAh);
            int rbase = reg ? n0 : m0;
            uint32_t dst = st + (uint32_t)(reg * BOFF + row * 128 + ((c ^ (row & 7)) * 16));
            cp16(dst, (const char*)src + ((size_t)(rbase + row) * K + kc * 32 + cc * 8) * 2);
        }
        cp_commit();
    };

    float acc[4][4][4];
#pragma unroll
    for (int mi = 0; mi < 4; mi++)
#pragma unroll
        for (int ni = 0; ni < 4; ni++)
#pragma unroll
            for (int j = 0; j < 4; j++) acc[mi][ni][j] = 0.f;

    const int rowa = wm * 64 + (lane & 15);
    const int ka   = lane >> 4;
    const int xa   = rowa & 7;
    const int rowb = wn * 32 + (lane & 7) + ((lane >> 4) << 3);
    const int kb   = (lane >> 3) & 1;
    const int xb   = rowb & 7;

    auto compute = [&](int s) {
        uint32_t st = sbase + s * STAGE;
#pragma unroll
        for (int ks = 0; ks < 2; ks++) {
            uint32_t ah[4][4], al[4][4], bh[2][4];
#pragma unroll
            for (int mi = 0; mi < 4; mi++) {
                uint32_t rb = st + (uint32_t)((rowa + mi * 16) * 128);
                ldsm4(ah[mi], rb + (uint32_t)(((2 * ks + ka) ^ xa) * 16));
                ldsm4(al[mi], rb + (uint32_t)(((4 + 2 * ks + ka) ^ xa) * 16));
            }
#pragma unroll
            for (int j = 0; j < 2; j++) {
                uint32_t rb = st + BOFF + (uint32_t)((rowb + j * 16) * 128);
                ldsm4(bh[j], rb + (uint32_t)(((2 * ks + kb) ^ xb) * 16));
            }
#pragma unroll
            for (int mi = 0; mi < 4; mi++)
#pragma unroll
                for (int j = 0; j < 2; j++) {
                    mma16816(acc[mi][2 * j],     ah[mi], bh[j]);
                    mma16816(acc[mi][2 * j + 1], ah[mi], bh[j] + 2);
                }
#pragma unroll
            for (int mi = 0; mi < 4; mi++)
#pragma unroll
                for (int j = 0; j < 2; j++) {
                    mma16816(acc[mi][2 * j],     al[mi], bh[j]);
                    mma16816(acc[mi][2 * j + 1], al[mi], bh[j] + 2);
                }
        }
    };

    load(0, 0);
    if (KT > 1) load(1, 1);

    for (int ci = 0; ci < KT; ci++) {
        if (ci < KT - 1) cp_wait<1>(); else cp_wait<0>();
        __syncthreads();
        if (ci + 2 < KT) load(ci + 2, (ci + 2) % 3);
        compute(ci % 3);
    }

    float* Co = C + (size_t)b * sC;
    const float* Rp = ADD ? (Res + (size_t)b * sC) : nullptr;
    const int rbase = m0 + wm * 64 + (lane >> 2);
    const int cbase = n0 + wn * 32 + (lane & 3) * 2;
#pragma unroll
    for (int mi = 0; mi < 4; mi++) {
#pragma unroll
        for (int ni = 0; ni < 4; ni++) {
#pragma unroll
            for (int h = 0; h < 2; h++) {
                int r = rbase + mi * 16 + h * 8;
                int c = cbase + ni * 8;
                float2 v;
                v.x = acc[mi][ni][2 * h]     * scale;
                v.y = acc[mi][ni][2 * h + 1] * scale;
                size_t go = (size_t)r * Nglob + c;
                if (ADD) {
                    float2 d = *(const float2*)(Rp + go);
                    v.x += d.x; v.y += d.y;
                }
                *(float2*)(Co + go) = v;
            }
        }
    }
}

// ---------------- fused conversion kernels ----------------
// split (hi+lo) + transposed split (hi only) in one pass
__global__ void stx_k(const float* __restrict__ in, hf* __restrict__ oh,
                      hf* __restrict__ ol, hf* __restrict__ ohT, int R, int Cc)
{
    __shared__ float t[32][33];
    int b = blockIdx.z;
    int c0 = blockIdx.x * 32, r0 = blockIdx.y * 32;
    const float* ip = in + (size_t)b * R * Cc;
    size_t nb = (size_t)b * R * Cc;
    int tx = threadIdx.x, ty = threadIdx.y;
#pragma unroll
    for (int i = 0; i < 4; i++) {
        int r = r0 + ty + i * 8;
        float v = ip[(size_t)r * Cc + c0 + tx];
        t[ty + i * 8][tx] = v;
        hf h, l;
        split1(v, h, l);
        oh[nb + (size_t)r * Cc + c0 + tx] = h;
        if (ol) ol[nb + (size_t)r * Cc + c0 + tx] = l;
    }
    __syncthreads();
#pragma unroll
    for (int i = 0; i < 4; i++) {
        int c = c0 + ty + i * 8;
        ohT[nb + (size_t)c * R + r0 + tx] = __float2half_rn(t[tx][ty + i * 8]);
    }
}

// hi-only conversion (K)
__global__ void splith_k(const float* __restrict__ in, hf* __restrict__ h, size_t n4)
{
    size_t i = (size_t)blockIdx.x * blockDim.x + threadIdx.x;
    if (i >= n4) return;
    float4 v = ((const float4*)in)[i];
    __half2* hp = (__half2*)h;
    hp[i * 2]     = __halves2half2(__float2half_rn(v.x), __float2half_rn(v.y));
    hp[i * 2 + 1] = __halves2half2(__float2half_rn(v.z), __float2half_rn(v.w));
}

__global__ void softrow512_k(const float* __restrict__ S, hf* __restrict__ oh,
                             hf* __restrict__ ol)
{
    int warp = threadIdx.x >> 5, lane = threadIdx.x & 31;
    size_t row = (size_t)blockIdx.x * 8 + warp;
    const float4* p4 = (const float4*)(S + row * SDIM);
    float4 v[4];
    float m = NEG_INF;
#pragma unroll
    for (int i = 0; i < 4; i++) {
        v[i] = p4[lane + i * 32];
        m = fmaxf(m, fmaxf(fmaxf(v[i].x, v[i].y), fmaxf(v[i].z, v[i].w)));
    }
#pragma unroll
    for (int o = 16; o > 0; o >>= 1) m = fmaxf(m, __shfl_xor_sync(0xffffffffu, m, o));
    float s = 0.f;
#pragma unroll
    for (int i = 0; i < 4; i++)
        s += __expf(v[i].x - m) + __expf(v[i].y - m) + __expf(v[i].z - m) + __expf(v[i].w - m);
#pragma unroll
    for (int o = 16; o > 0; o >>= 1) s += __shfl_xor_sync(0xffffffffu, s, o);
    float inv = __fdividef(1.0f, s);
    __half2* hp = (__half2*)(oh + row * SDIM);
    __half2* lp = (__half2*)(ol + row * SDIM);
#pragma unroll
    for (int i = 0; i < 4; i++) {
        hf h0, l0, h1, l1, h2, l2, h3, l3;
        split1(__expf(v[i].x - m) * inv, h0, l0);
        split1(__expf(v[i].y - m) * inv, h1, l1);
        split1(__expf(v[i].z - m) * inv, h2, l2);
        split1(__expf(v[i].w - m) * inv, h3, l3);
        int p = (lane + i * 32) * 2;
        hp[p]     = __halves2half2(h0, h1);
        hp[p + 1] = __halves2half2(h2, h3);
        lp[p]     = __halves2half2(l0, l1);
        lp[p + 1] = __halves2half2(l2, l3);
    }
}

__global__ void softrow4096_k(const float* __restrict__ S, hf* __restrict__ oh,
                              hf* __restrict__ ol)
{
    __shared__ float sh[16];
    int tid = threadIdx.x, lane = tid & 31, warp = tid >> 5;
    size_t row = blockIdx.x;
    const float4* p4 = (const float4*)(S + row * TDIM);
    float4 v[2];
    float m = NEG_INF;
#pragma unroll
    for (int i = 0; i < 2; i++) {
        v[i] = p4[tid + i * 512];
        m = fmaxf(m, fmaxf(fmaxf(v[i].x, v[i].y), fmaxf(v[i].z, v[i].w)));
    }
#pragma unroll
    for (int o = 16; o > 0; o >>= 1) m = fmaxf(m, __shfl_xor_sync(0xffffffffu, m, o));
    if (!lane) sh[warp] = m;
    __syncthreads();
    if (tid < 16) {
        float t = sh[tid];
#pragma unroll
        for (int o = 8; o > 0; o >>= 1) t = fmaxf(t, __shfl_xor_sync(0xffffu, t, o));
        if (!tid) sh[0] = t;
    }
    __syncthreads();
    m = sh[0];
    __syncthreads();
    float s = 0.f;
#pragma unroll
    for (int i = 0; i < 2; i++)
        s += __expf(v[i].x - m) + __expf(v[i].y - m) + __expf(v[i].z - m) + __expf(v[i].w - m);
#pragma unroll
    for (int o = 16; o > 0; o >>= 1) s += __shfl_xor_sync(0xffffffffu, s, o);
    if (!lane) sh[warp] = s;
    __syncthreads();
    if (tid < 16) {
        float t = sh[tid];
#pragma unroll
        for (int o = 8; o > 0; o >>= 1) t += __shfl_xor_sync(0xffffu, t, o);
        if (!tid) sh[0] = t;
    }
    __syncthreads();
    float inv = __fdividef(1.0f, sh[0]);
    __half2* hp = (__half2*)(oh + row * TDIM);
    __half2* lp = (__half2*)(ol + row * TDIM);
#pragma unroll
    for (int i = 0; i < 2; i++) {
        hf h0, l0, h1, l1, h2, l2, h3, l3;
        split1(__expf(v[i].x - m) * inv, h0, l0);
        split1(__expf(v[i].y - m) * inv, h1, l1);
        split1(__expf(v[i].z - m) * inv, h2, l2);
        split1(__expf(v[i].w - m) * inv, h3, l3);
        int p = (tid + i * 512) * 2;
        hp[p]     = __halves2half2(h0, h1);
        hp[p + 1] = __halves2half2(h2, h3);
        lp[p]     = __halves2half2(l0, l1);
        lp[p + 1] = __halves2half2(l2, l3);
    }
}

// ---------------- column softmax (over T) pipeline ----------------
__global__ void colpart_k(const float* __restrict__ S, float* __restrict__ pm,
                          float* __restrict__ ps)
{
    int b = blockIdx.y, ch = blockIdx.x, s = threadIdx.x;
    const float* p = S + (size_t)b * TDIM * SDIM + (size_t)ch * CHROWS * SDIM + s;
    float m = NEG_INF, sum = 0.f;
    for (int t = 0; t < CHROWS; t++) {
        float v = p[(size_t)t * SDIM];
        float nm = fmaxf(m, v);
        sum = sum * __expf(m - nm) + __expf(v - nm);
        m = nm;
    }
    int o = (b * NCHUNK + ch) * SDIM + s;
    pm[o] = m; ps[o] = sum;
}

__global__ void colcomb_k(const float* __restrict__ pm, const float* __restrict__ ps,
                          float* __restrict__ cm, float* __restrict__ cs)
{
    int b = blockIdx.x, s = threadIdx.x;
    float m = NEG_INF;
#pragma unroll
    for (int c = 0; c < NCHUNK; c++) m = fmaxf(m, pm[(b * NCHUNK + c) * SDIM + s]);
    float sum = 0.f;
#pragma unroll
    for (int c = 0; c < NCHUNK; c++)
        sum += ps[(b * NCHUNK + c) * SDIM + s] * __expf(pm[(b * NCHUNK + c) * SDIM + s] - m);
    cm[b * SDIM + s] = m;
    cs[b * SDIM + s] = sum;
}

__global__ void pcolT_k(const float* __restrict__ sc, const float* __restrict__ cm,
                        const float* __restrict__ cs, hf* __restrict__ oh,
                        hf* __restrict__ ol)
{
    __shared__ float t[32][33];
    int b = blockIdx.z;
    int s0 = blockIdx.x * 32, t0 = blockIdx.y * 32;
    const float* ip = sc + (size_t)b * TDIM * SDIM;
    int tx = threadIdx.x, ty = threadIdx.y;
#pragma unroll
    for (int i = 0; i < 4; i++)
        t[ty + i * 8][tx] = ip[(size_t)(t0 + ty + i * 8) * SDIM + s0 + tx];
    __syncthreads();
    size_t ob = (size_t)b * SDIM * TDIM;
#pragma unroll
    for (int i = 0; i < 4; i++) {
        int s = s0 + ty + i * 8;
        float m = cm[b * SDIM + s], inv = __fdividef(1.0f, cs[b * SDIM + s]);
        hf h, l;
        split1(__expf(t[tx][ty + i * 8] - m) * inv, h, l);
        oh[ob + (size_t)s * TDIM + t0 + tx] = h;
        ol[ob + (size_t)s * TDIM + t0 + tx] = l;
    }
}

// ---------------- launch ----------------
extern "C" void kernel_launch(void* const* d_in, const int* in_sizes, int n_in,
                              void* d_out, int out_size)
{
    const float* x   = (const float*)d_in[0];
    const float* kin = (const float*)d_in[1];
    const float* vin = (const float*)d_in[2];

    float* att = (float*)d_out;
    float* ktv = att + (size_t)NB * TDIM * CDIM;
    float* vtv = ktv + (size_t)NB * SDIM * CDIM;

    float *sc, *vsc, *pcm, *pcs, *cm, *cs;
    hf *Xh, *Xl, *XTh, *Kh, *Vh, *Vl, *VTh;
    hf *Ph, *Pl, *P2h, *P2l, *P3h, *P3l;
    cudaGetSymbolAddress((void**)&sc, g_sc);     cudaGetSymbolAddress((void**)&vsc, g_vsc);
    cudaGetSymbolAddress((void**)&pcm, g_pcm);   cudaGetSymbolAddress((void**)&pcs, g_pcs);
    cudaGetSymbolAddress((void**)&cm, g_cm);     cudaGetSymbolAddress((void**)&cs, g_cs);
    cudaGetSymbolAddress((void**)&Xh, g_Xh);     cudaGetSymbolAddress((void**)&Xl, g_Xl);
    cudaGetSymbolAddress((void**)&XTh, g_XTh);
    cudaGetSymbolAddress((void**)&Kh, g_Kh);
    cudaGetSymbolAddress((void**)&Vh, g_Vh);     cudaGetSymbolAddress((void**)&Vl, g_Vl);
    cudaGetSymbolAddress((void**)&VTh, g_VTh);
    cudaGetSymbolAddress((void**)&Ph, g_Ph);     cudaGetSymbolAddress((void**)&Pl, g_Pl);
    cudaGetSymbolAddress((void**)&P2h, g_P2h);   cudaGetSymbolAddress((void**)&P2l, g_P2l);
    cudaGetSymbolAddress((void**)&P3h, g_P3h);   cudaGetSymbolAddress((void**)&P3l, g_P3l);

    const int SMEM = 3 * STAGE;  // 98304
    cudaFuncSetAttribute(mma_gemm<false>, cudaFuncAttributeMaxDynamicSharedMemorySize, SMEM);
    cudaFuncSetAttribute(mma_gemm<true>,  cudaFuncAttributeMaxDynamicSharedMemorySize, SMEM);

    const float scale = 0.03125f;  // 1/sqrt(1024)

    // operand prep
    stx_k<<<dim3(CDIM / 32, TDIM / 32, NB), dim3(32, 8)>>>(x, Xh, Xl, XTh, TDIM, CDIM);
    {
        size_t n4 = (size_t)NB * SDIM * CDIM / 4;
        splith_k<<<(unsigned)((n4 + 255) / 256), 256>>>(kin, Kh, n4);
    }
    stx_k<<<dim3(CDIM / 32, SDIM / 32, NB), dim3(32, 8)>>>(vin, Vh, Vl, VTh, SDIM, CDIM);

    // 1) scores = scale * X K^T  [T,S]  (2-pass; B = K hi)
    mma_gemm<false><<<dim3(SDIM / 128, TDIM / 128, NB), 256, SMEM>>>(
        Xh, Xl, Kh, nullptr, sc, scale, CDIM, SDIM,
        (size_t)TDIM * CDIM, (size_t)SDIM * CDIM, (size_t)TDIM * SDIM);

    // softmax conversions
    softrow512_k<<<NB * TDIM / 8, 256>>>(sc, Ph, Pl);
    colpart_k<<<dim3(NCHUNK, NB), 512>>>(sc, pcm, pcs);
    colcomb_k<<<NB, 512>>>(pcm, pcs, cm, cs);
    pcolT_k<<<dim3(SDIM / 32, TDIM / 32, NB), dim3(32, 8)>>>(sc, cm, cs, P2h, P2l);

    // 2) att = P V   (2-pass; B = V^T hi, K=512)
    mma_gemm<false><<<dim3(CDIM / 128, TDIM / 128, NB), 256, SMEM>>>(
        Ph, Pl, VTh, nullptr, att, 1.0f, SDIM, CDIM,
        (size_t)TDIM * SDIM, (size_t)CDIM * SDIM, (size_t)TDIM * CDIM);

    // 3) k_t = k + P2^T X   (2-pass; B = X^T hi, K=4096)
    mma_gemm<true><<<dim3(CDIM / 128, SDIM / 128, NB), 256, SMEM>>>(
        P2h, P2l, XTh, kin, ktv, 1.0f, TDIM, CDIM,
        (size_t)SDIM * TDIM, (size_t)CDIM * TDIM, (size_t)SDIM * CDIM);

    // 4) v_scores = scale * V X^T  [S,T]  (2-pass; B = X hi)
    mma_gemm<false><<<dim3(TDIM / 128, SDIM / 128, NB), 256, SMEM>>>(
        Vh, Vl, Xh, nullptr, vsc, scale, CDIM, TDIM,
        (size_t)SDIM * CDIM, (size_t)TDIM * CDIM, (size_t)SDIM * TDIM);

    // P3 (row softmax over 4096)
    softrow4096_k<<<NB * SDIM, 512>>>(vsc, P3h, P3l);

    // 5) v_t = v + P3 X   (2-pass; B = X^T hi, K=4096)
    mma_gemm<true><<<dim3(CDIM / 128, SDIM / 128, NB), 256, SMEM>>>(
        P3h, P3l, XTh, vin, vtv, 1.0f, TDIM, CDIM,
        (size_t)SDIM * TDIM, (size_t)CDIM * TDIM, (size_t)SDIM * CDIM);
}

// round 8
// speedup vs baseline: 1.8511x; 1.1872x over previous
#include <cuda_runtime.h>
#include <cuda_fp16.h>
#include <cstdint>

#define NB 8
#define TDIM 4096
#define SDIM 512
#define CDIM 1024
#define NCHUNK 16
#define CHROWS (TDIM / NCHUNK)
#define NEG_INF (-3.0e38f)

typedef __half hf;

// ---------------- scratch (static device globals; no allocation) ----------------
__device__ float g_sc [(size_t)NB * TDIM * SDIM];
__device__ float g_vsc[(size_t)NB * SDIM * TDIM];
__device__ __align__(16) hf g_Xh [(size_t)NB * TDIM * CDIM], g_Xl [(size_t)NB * TDIM * CDIM];
__device__ __align__(16) hf g_XTh[(size_t)NB * CDIM * TDIM];
__device__ __align__(16) hf g_Kh [(size_t)NB * SDIM * CDIM];
__device__ __align__(16) hf g_Vh [(size_t)NB * SDIM * CDIM], g_Vl [(size_t)NB * SDIM * CDIM];
__device__ __align__(16) hf g_VTh[(size_t)NB * CDIM * SDIM];
__device__ __align__(16) hf g_Ph [(size_t)NB * TDIM * SDIM], g_Pl [(size_t)NB * TDIM * SDIM];
__device__ __align__(16) hf g_P2h[(size_t)NB * SDIM * TDIM];
__device__ __align__(16) hf g_P3h[(size_t)NB * SDIM * TDIM];
__device__ float g_pcm[NB * NCHUNK * SDIM], g_pcs[NB * NCHUNK * SDIM];
__device__ float g_cm [NB * SDIM], g_cs [NB * SDIM];

// ---------------- PTX helpers ----------------
__device__ __forceinline__ void cp16(uint32_t dst, const void* src) {
    asm volatile("cp.async.cg.shared.global [%0], [%1], 16;" :: "r"(dst), "l"(src));
}
__device__ __forceinline__ void cp_commit() {
    asm volatile("cp.async.commit_group;" ::: "memory");
}
template <int N>
__device__ __forceinline__ void cp_wait() {
    asm volatile("cp.async.wait_group %0;" :: "n"(N) : "memory");
}
__device__ __forceinline__ void ldsm4(uint32_t* r, uint32_t addr) {
    asm volatile("ldmatrix.sync.aligned.m8n8.x4.shared.b16 {%0,%1,%2,%3}, [%4];"
                 : "=r"(r[0]), "=r"(r[1]), "=r"(r[2]), "=r"(r[3]) : "r"(addr));
}
__device__ __forceinline__ void mma16816(float* d, const uint32_t* a, const uint32_t* b) {
    asm volatile(
        "mma.sync.aligned.m16n8k16.row.col.f32.f16.f16.f32 "
        "{%0,%1,%2,%3}, {%4,%5,%6,%7}, {%8,%9}, {%0,%1,%2,%3};"
        : "+f"(d[0]), "+f"(d[1]), "+f"(d[2]), "+f"(d[3])
        : "r"(a[0]), "r"(a[1]), "r"(a[2]), "r"(a[3]), "r"(b[0]), "r"(b[1]));
}
__device__ __forceinline__ void split1(float f, hf& h, hf& l) {
    h = __float2half_rn(f);
    l = __float2half_rn(f - __half2float(h));
}

// ---------------------------------------------------------------------------
// fp16 emulated GEMM on HMMA. Tile 128x128, BK=32, 256 thr, warp tile 64x32;
// 3-stage cp.async, 2 CTAs/SM.
// PASSES=2: D = Ah*Bh + Al*Bh.   PASSES=1: D = Ah*Bh (A-lo never loaded).
// ---------------------------------------------------------------------------
#define STAGE 32768
#define BOFF  16384

template <int PASSES, bool ADD>
__global__ void __launch_bounds__(256, 2)
mma_gemm(const hf* __restrict__ Ah, const hf* __restrict__ Al,
         const hf* __restrict__ Bh,
         const float* __restrict__ Res, float* __restrict__ C,
         float scale, int K, int Nglob, size_t sA, size_t sB, size_t sC)
{
    extern __shared__ char dsm[];
    const uint32_t sbase = (uint32_t)__cvta_generic_to_shared(dsm);
    const int tid = threadIdx.x, wid = tid >> 5, lane = tid & 31;
    const int b = blockIdx.z, m0 = blockIdx.y * 128, n0 = blockIdx.x * 128;
    const int wm = wid & 1, wn = wid >> 1;

    const hf* pAh = Ah + (size_t)b * sA;
    const hf* pAl = (PASSES == 2) ? (Al + (size_t)b * sA) : nullptr;
    const hf* pBh = Bh + (size_t)b * sB;

    const int KT = K >> 5;

    auto load = [&](int kc, int s) {
        uint32_t st = sbase + s * STAGE;
#pragma unroll
        for (int t = 0; t < 8; t++) {
            int idx = t * 256 + tid;
            int reg = idx >> 10;               // 0 = A, 1 = B
            int ch  = idx & 1023;
            int row = ch >> 3, c = ch & 7;
            int plane = c >> 2, cc = c & 3;    // hi chunks 0-3, lo chunks 4-7
            if (plane == 1 && (reg == 1 || PASSES == 1)) continue;  // no B-lo; no A-lo if 1-pass
            const hf* src = reg ? pBh : (plane ? pAl : pAh);
            int rbase = reg ? n0 : m0;
            uint32_t dst = st + (uint32_t)(reg * BOFF + row * 128 + ((c ^ (row & 7)) * 16));
            cp16(dst, (const char*)src + ((size_t)(rbase + row) * K + kc * 32 + cc * 8) * 2);
        }
        cp_commit();
    };

    float acc[4][4][4];
#pragma unroll
    for (int mi = 0; mi < 4; mi++)
#pragma unroll
        for (int ni = 0; ni < 4; ni++)
#pragma unroll
            for (int j = 0; j < 4; j++) acc[mi][ni][j] = 0.f;

    const int rowa = wm * 64 + (lane & 15);
    const int ka   = lane >> 4;
    const int xa   = rowa & 7;
    const int rowb = wn * 32 + (lane & 7) + ((lane >> 4) << 3);
    const int kb   = (lane >> 3) & 1;
    const int xb   = rowb & 7;

    auto compute = [&](int s) {
        uint32_t st = sbase + s * STAGE;
#pragma unroll
        for (int ks = 0; ks < 2; ks++) {
            uint32_t ah[4][4], al[4][4], bh[2][4];
#pragma unroll
            for (int mi = 0; mi < 4; mi++) {
                uint32_t rb = st + (uint32_t)((rowa + mi * 16) * 128);
                ldsm4(ah[mi], rb + (uint32_t)(((2 * ks + ka) ^ xa) * 16));
                if (PASSES == 2)
                    ldsm4(al[mi], rb + (uint32_t)(((4 + 2 * ks + ka) ^ xa) * 16));
            }
#pragma unroll
            for (int j = 0; j < 2; j++) {
                uint32_t rb = st + BOFF + (uint32_t)((rowb + j * 16) * 128);
                ldsm4(bh[j], rb + (uint32_t)(((2 * ks + kb) ^ xb) * 16));
            }
#pragma unroll
            for (int mi = 0; mi < 4; mi++)
#pragma unroll
                for (int j = 0; j < 2; j++) {
                    mma16816(acc[mi][2 * j],     ah[mi], bh[j]);
                    mma16816(acc[mi][2 * j + 1], ah[mi], bh[j] + 2);
                }
            if (PASSES == 2) {
#pragma unroll
                for (int mi = 0; mi < 4; mi++)
#pragma unroll
                    for (int j = 0; j < 2; j++) {
                        mma16816(acc[mi][2 * j],     al[mi], bh[j]);
                        mma16816(acc[mi][2 * j + 1], al[mi], bh[j] + 2);
                    }
            }
        }
    };

    load(0, 0);
    if (KT > 1) load(1, 1);

    for (int ci = 0; ci < KT; ci++) {
        if (ci < KT - 1) cp_wait<1>(); else cp_wait<0>();
        __syncthreads();
        if (ci + 2 < KT) load(ci + 2, (ci + 2) % 3);
        compute(ci % 3);
    }

    float* Co = C + (size_t)b * sC;
    const float* Rp = ADD ? (Res + (size_t)b * sC) : nullptr;
    const int rbase = m0 + wm * 64 + (lane >> 2);
    const int cbase = n0 + wn * 32 + (lane & 3) * 2;
#pragma unroll
    for (int mi = 0; mi < 4; mi++) {
#pragma unroll
        for (int ni = 0; ni < 4; ni++) {
#pragma unroll
            for (int h = 0; h < 2; h++) {
                int r = rbase + mi * 16 + h * 8;
                int c = cbase + ni * 8;
                float2 v;
                v.x = acc[mi][ni][2 * h]     * scale;
                v.y = acc[mi][ni][2 * h + 1] * scale;
                size_t go = (size_t)r * Nglob + c;
                if (ADD) {
                    float2 d = *(const float2*)(Rp + go);
                    v.x += d.x; v.y += d.y;
                }
                *(float2*)(Co + go) = v;
            }
        }
    }
}

// ---------------- fused conversion kernels ----------------
// split (hi+lo) + transposed split (hi only) in one pass
__global__ void stx_k(const float* __restrict__ in, hf* __restrict__ oh,
                      hf* __restrict__ ol, hf* __restrict__ ohT, int R, int Cc)
{
    __shared__ float t[32][33];
    int b = blockIdx.z;
    int c0 = blockIdx.x * 32, r0 = blockIdx.y * 32;
    const float* ip = in + (size_t)b * R * Cc;
    size_t nb = (size_t)b * R * Cc;
    int tx = threadIdx.x, ty = threadIdx.y;
#pragma unroll
    for (int i = 0; i < 4; i++) {
        int r = r0 + ty + i * 8;
        float v = ip[(size_t)r * Cc + c0 + tx];
        t[ty + i * 8][tx] = v;
        hf h, l;
        split1(v, h, l);
        oh[nb + (size_t)r * Cc + c0 + tx] = h;
        if (ol) ol[nb + (size_t)r * Cc + c0 + tx] = l;
    }
    __syncthreads();
#pragma unroll
    for (int i = 0; i < 4; i++) {
        int c = c0 + ty + i * 8;
        ohT[nb + (size_t)c * R + r0 + tx] = __float2half_rn(t[tx][ty + i * 8]);
    }
}

// hi-only conversion (K)
__global__ void splith_k(const float* __restrict__ in, hf* __restrict__ h, size_t n4)
{
    size_t i = (size_t)blockIdx.x * blockDim.x + threadIdx.x;
    if (i >= n4) return;
    float4 v = ((const float4*)in)[i];
    __half2* hp = (__half2*)h;
    hp[i * 2]     = __halves2half2(__float2half_rn(v.x), __float2half_rn(v.y));
    hp[i * 2 + 1] = __halves2half2(__float2half_rn(v.z), __float2half_rn(v.w));
}

__global__ void softrow512_k(const float* __restrict__ S, hf* __restrict__ oh,
                             hf* __restrict__ ol)
{
    int warp = threadIdx.x >> 5, lane = threadIdx.x & 31;
    size_t row = (size_t)blockIdx.x * 8 + warp;
    const float4* p4 = (const float4*)(S + row * SDIM);
    float4 v[4];
    float m = NEG_INF;
#pragma unroll
    for (int i = 0; i < 4; i++) {
        v[i] = p4[lane + i * 32];
        m = fmaxf(m, fmaxf(fmaxf(v[i].x, v[i].y), fmaxf(v[i].z, v[i].w)));
    }
#pragma unroll
    for (int o = 16; o > 0; o >>= 1) m = fmaxf(m, __shfl_xor_sync(0xffffffffu, m, o));
    float s = 0.f;
#pragma unroll
    for (int i = 0; i < 4; i++)
        s += __expf(v[i].x - m) + __expf(v[i].y - m) + __expf(v[i].z - m) + __expf(v[i].w - m);
#pragma unroll
    for (int o = 16; o > 0; o >>= 1) s += __shfl_xor_sync(0xffffffffu, s, o);
    float inv = __fdividef(1.0f, s);
    __half2* hp = (__half2*)(oh + row * SDIM);
    __half2* lp = (__half2*)(ol + row * SDIM);
#pragma unroll
    for (int i = 0; i < 4; i++) {
        hf h0, l0, h1, l1, h2, l2, h3, l3;
        split1(__expf(v[i].x - m) * inv, h0, l0);
        split1(__expf(v[i].y - m) * inv, h1, l1);
        split1(__expf(v[i].z - m) * inv, h2, l2);
        split1(__expf(v[i].w - m) * inv, h3, l3);
        int p = (lane + i * 32) * 2;
        hp[p]     = __halves2half2(h0, h1);
        hp[p + 1] = __halves2half2(h2, h3);
        lp[p]     = __halves2half2(l0, l1);
        lp[p + 1] = __halves2half2(l2, l3);
    }
}

// row softmax over 4096 -> fp16 hi only
__global__ void softrow4096_k(const float* __restrict__ S, hf* __restrict__ oh)
{
    __shared__ float sh[16];
    int tid = threadIdx.x, lane = tid & 31, warp = tid >> 5;
    size_t row = blockIdx.x;
    const float4* p4 = (const float4*)(S + row * TDIM);
    float4 v[2];
    float m = NEG_INF;
#pragma unroll
    for (int i = 0; i < 2; i++) {
        v[i] = p4[tid + i * 512];
        m = fmaxf(m, fmaxf(fmaxf(v[i].x, v[i].y), fmaxf(v[i].z, v[i].w)));
    }
#pragma unroll
    for (int o = 16; o > 0; o >>= 1) m = fmaxf(m, __shfl_xor_sync(0xffffffffu, m, o));
    if (!lane) sh[warp] = m;
    __syncthreads();
    if (tid < 16) {
        float t = sh[tid];
#pragma unroll
        for (int o = 8; o > 0; o >>= 1) t = fmaxf(t, __shfl_xor_sync(0xffffu, t, o));
        if (!tid) sh[0] = t;
    }
    __syncthreads();
    m = sh[0];
    __syncthreads();
    float s = 0.f;
#pragma unroll
    for (int i = 0; i < 2; i++)
        s += __expf(v[i].x - m) + __expf(v[i].y - m) + __expf(v[i].z - m) + __expf(v[i].w - m);
#pragma unroll
    for (int o = 16; o > 0; o >>= 1) s += __shfl_xor_sync(0xffffffffu, s, o);
    if (!lane) sh[warp] = s;
    __syncthreads();
    if (tid < 16) {
        float t = sh[tid];
#pragma unroll
        for (int o = 8; o > 0; o >>= 1) t += __shfl_xor_sync(0xffffu, t, o);
        if (!tid) sh[0] = t;
    }
    __syncthreads();
    float inv = __fdividef(1.0f, sh[0]);
    __half2* hp = (__half2*)(oh + row * TDIM);
#pragma unroll
    for (int i = 0; i < 2; i++) {
        int p = (tid + i * 512) * 2;
        hp[p]     = __halves2half2(__float2half_rn(__expf(v[i].x - m) * inv),
                                   __float2half_rn(__expf(v[i].y - m) * inv));
        hp[p + 1] = __halves2half2(__float2half_rn(__expf(v[i].z - m) * inv),
                                   __float2half_rn(__expf(v[i].w - m) * inv));
    }
}

// ---------------- column softmax (over T) pipeline ----------------
__global__ void colpart_k(const float* __restrict__ S, float* __restrict__ pm,
                          float* __restrict__ ps)
{
    int b = blockIdx.y, ch = blockIdx.x, s = threadIdx.x;
    const float* p = S + (size_t)b * TDIM * SDIM + (size_t)ch * CHROWS * SDIM + s;
    float m = NEG_INF, sum = 0.f;
    for (int t = 0; t < CHROWS; t++) {
        float v = p[(size_t)t * SDIM];
        float nm = fmaxf(m, v);
        sum = sum * __expf(m - nm) + __expf(v - nm);
        m = nm;
    }
    int o = (b * NCHUNK + ch) * SDIM + s;
    pm[o] = m; ps[o] = sum;
}

__global__ void colcomb_k(const float* __restrict__ pm, const float* __restrict__ ps,
                          float* __restrict__ cm, float* __restrict__ cs)
{
    int b = blockIdx.x, s = threadIdx.x;
    float m = NEG_INF;
#pragma unroll
    for (int c = 0; c < NCHUNK; c++) m = fmaxf(m, pm[(b * NCHUNK + c) * SDIM + s]);
    float sum = 0.f;
#pragma unroll
    for (int c = 0; c < NCHUNK; c++)
        sum += ps[(b * NCHUNK + c) * SDIM + s] * __expf(pm[(b * NCHUNK + c) * SDIM + s] - m);
    cm[b * SDIM + s] = m;
    cs[b * SDIM + s] = sum;
}

// col softmax + transpose -> [S,T] fp16 hi only
__global__ void pcolT_k(const float* __restrict__ sc, const float* __restrict__ cm,
                        const float* __restrict__ cs, hf* __restrict__ oh)
{
    __shared__ float t[32][33];
    int b = blockIdx.z;
    int s0 = blockIdx.x * 32, t0 = blockIdx.y * 32;
    const float* ip = sc + (size_t)b * TDIM * SDIM;
    int tx = threadIdx.x, ty = threadIdx.y;
#pragma unroll
    for (int i = 0; i < 4; i++)
        t[ty + i * 8][tx] = ip[(size_t)(t0 + ty + i * 8) * SDIM + s0 + tx];
    __syncthreads();
    size_t ob = (size_t)b * SDIM * TDIM;
#pragma unroll
    for (int i = 0; i < 4; i++) {
        int s = s0 + ty + i * 8;
        float m = cm[b * SDIM + s], inv = __fdividef(1.0f, cs[b * SDIM + s]);
        oh[ob + (size_t)s * TDIM + t0 + tx] =
            __float2half_rn(__expf(t[tx][ty + i * 8] - m) * inv);
    }
}

// ---------------- launch ----------------
extern "C" void kernel_launch(void* const* d_in, const int* in_sizes, int n_in,
                              void* d_out, int out_size)
{
    const float* x   = (const float*)d_in[0];
    const float* kin = (const float*)d_in[1];
    const float* vin = (const float*)d_in[2];

    float* att = (float*)d_out;
    float* ktv = att + (size_t)NB * TDIM * CDIM;
    float* vtv = ktv + (size_t)NB * SDIM * CDIM;

    float *sc, *vsc, *pcm, *pcs, *cm, *cs;
    hf *Xh, *Xl, *XTh, *Kh, *Vh, *Vl, *VTh;
    hf *Ph, *Pl, *P2h, *P3h;
    cudaGetSymbolAddress((void**)&sc, g_sc);     cudaGetSymbolAddress((void**)&vsc, g_vsc);
    cudaGetSymbolAddress((void**)&pcm, g_pcm);   cudaGetSymbolAddress((void**)&pcs, g_pcs);
    cudaGetSymbolAddress((void**)&cm, g_cm);     cudaGetSymbolAddress((void**)&cs, g_cs);
    cudaGetSymbolAddress((void**)&Xh, g_Xh);     cudaGetSymbolAddress((void**)&Xl, g_Xl);
    cudaGetSymbolAddress((void**)&XTh, g_XTh);
    cudaGetSymbolAddress((void**)&Kh, g_Kh);
    cudaGetSymbolAddress((void**)&Vh, g_Vh);     cudaGetSymbolAddress((void**)&Vl, g_Vl);
    cudaGetSymbolAddress((void**)&VTh, g_VTh);
    cudaGetSymbolAddress((void**)&Ph, g_Ph);     cudaGetSymbolAddress((void**)&Pl, g_Pl);
    cudaGetSymbolAddress((void**)&P2h, g_P2h);
    cudaGetSymbolAddress((void**)&P3h, g_P3h);

    const int SMEM = 3 * STAGE;  // 98304
    cudaFuncSetAttribute(mma_gemm<2, false>, cudaFuncAttributeMaxDynamicSharedMemorySize, SMEM);
    cudaFuncSetAttribute(mma_gemm<1, true>,  cudaFuncAttributeMaxDynamicSharedMemorySize, SMEM);

    const float scale = 0.03125f;  // 1/sqrt(1024)

    // operand prep
    stx_k<<<dim3(CDIM / 32, TDIM / 32, NB), dim3(32, 8)>>>(x, Xh, Xl, XTh, TDIM, CDIM);
    {
        size_t n4 = (size_t)NB * SDIM * CDIM / 4;
        splith_k<<<(unsigned)((n4 + 255) / 256), 256>>>(kin, Kh, n4);
    }
    stx_k<<<dim3(CDIM / 32, SDIM / 32, NB), dim3(32, 8)>>>(vin, Vh, Vl, VTh, SDIM, CDIM);

    // 1) scores = scale * X K^T  [T,S]  (2-pass)
    mma_gemm<2, false><<<dim3(SDIM / 128, TDIM / 128, NB), 256, SMEM>>>(
        Xh, Xl, Kh, nullptr, sc, scale, CDIM, SDIM,
        (size_t)TDIM * CDIM, (size_t)SDIM * CDIM, (size_t)TDIM * SDIM);

    // softmax conversions
    softrow512_k<<<NB * TDIM / 8, 256>>>(sc, Ph, Pl);
    colpart_k<<<dim3(NCHUNK, NB), 512>>>(sc, pcm, pcs);
    colcomb_k<<<NB, 512>>>(pcm, pcs, cm, cs);
    pcolT_k<<<dim3(SDIM / 32, TDIM / 32, NB), dim3(32, 8)>>>(sc, cm, cs, P2h);

    // 2) att = P V   (2-pass; K=512)
    mma_gemm<2, false><<<dim3(CDIM / 128, TDIM / 128, NB), 256, SMEM>>>(
        Ph, Pl, VTh, nullptr, att, 1.0f, SDIM, CDIM,
        (size_t)TDIM * SDIM, (size_t)CDIM * SDIM, (size_t)TDIM * CDIM);

    // 3) k_t = k + P2^T X   (1-pass; residual-dominated, K=4096)
    mma_gemm<1, true><<<dim3(CDIM / 128, SDIM / 128, NB), 256, SMEM>>>(
        P2h, nullptr, XTh, kin, ktv, 1.0f, TDIM, CDIM,
        (size_t)SDIM * TDIM, (size_t)CDIM * TDIM, (size_t)SDIM * CDIM);

    // 4) v_scores = scale * V X^T  [S,T]  (2-pass)
    mma_gemm<2, false><<<dim3(TDIM / 128, SDIM / 128, NB), 256, SMEM>>>(
        Vh, Vl, Xh, nullptr, vsc, scale, CDIM, TDIM,
        (size_t)SDIM * CDIM, (size_t)TDIM * CDIM, (size_t)SDIM * TDIM);

    // P3 (row softmax over 4096, hi only)
    softrow4096_k<<<NB * SDIM, 512>>>(vsc, P3h);

    // 5) v_t = v + P3 X   (1-pass; residual-dominated, K=4096)
    mma_gemm<1, true><<<dim3(CDIM / 128, SDIM / 128, NB), 256, SMEM>>>(
        P3h, nullptr, XTh, vin, vtv, 1.0f, TDIM, CDIM,
        (size_t)SDIM * TDIM, (size_t)CDIM * TDIM, (size_t)SDIM * CDIM);
}